// round 6
// baseline (speedup 1.0000x reference)
#include <cuda_runtime.h>
#include <math.h>

// Problem constants
#define B_    4
#define L_    2048
#define DM    256     // d_model
#define DI    768     // d_inner
#define H_    256     // nheads
#define P_    3       // headdim
#define NS    16      // d_state
#define CD    800     // conv_dim = DI + 2*NS
#define DIP   1824    // d_in_proj
#define INC   128     // input channels
#define OC    128     // output channels
#define NC    16      // scan chunks
#define CHUNK 128     // L per chunk

// ------------------------- scratch (device globals; no malloc allowed) ----
__device__ float g_u   [B_*L_*DM];       // conv_in output, [b][l][c]
__device__ float g_z   [B_*L_*DI];       // gate branch
__device__ float g_xbc [B_*L_*CD];       // pre-dwconv
__device__ float g_xbc2[B_*L_*CD];       // post-dwconv+silu
__device__ float g_dt  [B_*L_*H_];       // softplus(dt + bias)
__device__ float g_dA  [B_*L_*H_];       // exp(dt * A)
__device__ float g_y   [B_*L_*DI];       // scan output -> normalized in place
__device__ float g_t1  [B_*L_*DM];       // out-proj result, [b][l][c]
__device__ float g_cs  [B_*H_*NC*P_*NS]; // per-chunk end states (from zero)
__device__ float g_hs  [B_*H_*NC*P_*NS]; // per-chunk start states
__device__ float g_cp  [B_*H_*NC];       // per-chunk decay products

// ------------------------- kernel 1: input conv (K=4, pad (1,2)) ----------
// u[b][l][co] = conv_b[co] + sum_{ci,k} x[b][ci][l+k-1] * conv_w[co][ci][k]
__global__ void __launch_bounds__(256)
conv_in_kernel(const float* __restrict__ x,
               const float* __restrict__ w,
               const float* __restrict__ bias) {
    __shared__ float xs[INC][36];   // 35 cols used (l0-1 .. l0+33)
    int b  = blockIdx.y;
    int l0 = blockIdx.x * 32;
    int tid = threadIdx.x;
    for (int i = tid; i < INC*35; i += 256) {
        int ci = i / 35, j = i % 35;
        int l = l0 - 1 + j;
        xs[ci][j] = (l >= 0 && l < L_) ? x[(b*INC + ci)*L_ + l] : 0.f;
    }
    __syncthreads();
    int co = tid;               // 256 threads = 256 output channels
    float bc = bias[co];
    for (int g = 0; g < 4; ++g) {
        int s0 = g * 8;
        float acc[8];
        #pragma unroll
        for (int s = 0; s < 8; ++s) acc[s] = bc;
        for (int ci = 0; ci < INC; ++ci) {
            float4 w4 = *(const float4*)&w[(co*INC + ci)*4];
            float xv[11];
            #pragma unroll
            for (int j = 0; j < 11; ++j) xv[j] = xs[ci][s0 + j];
            #pragma unroll
            for (int s = 0; s < 8; ++s)
                acc[s] += w4.x*xv[s] + w4.y*xv[s+1] + w4.z*xv[s+2] + w4.w*xv[s+3];
        }
        #pragma unroll
        for (int s = 0; s < 8; ++s)
            g_u[(b*L_ + l0 + s0 + s)*DM + co] = acc[s];
    }
}

// ------------------------- GEMM (fp32 SIMT, 64x64 tiles, 4x4/thread) ------
// MODE 0: A = g_u [8192,256], B = in_proj_w [256,1824]; epilogue splits z/xBC/dt
//         and fuses softplus + dA = exp(dt * -exp(A_log)).
// MODE 1: A = g_y [8192,768], B = mamba_out_w [768,256]; plain store to g_t1.
template<int MODE>
__global__ void __launch_bounds__(256)
gemm_kernel(const float* __restrict__ Bw,
            int M, int N, int K,
            const float* __restrict__ dt_bias,
            const float* __restrict__ A_log) {
    const float* A = (MODE == 0) ? g_u : g_y;
    __shared__ float As[16][64];   // [k][m]
    __shared__ float Bs[16][64];   // [k][n]
    int tid = threadIdx.x;
    int m0 = blockIdx.y * 64;
    int n0 = blockIdx.x * 64;
    int tx = tid & 15, ty = tid >> 4;
    float acc[4][4] = {};
    int a_m = tid >> 2, a_k = (tid & 3) * 4;
    int b_k = tid >> 4, b_n = (tid & 15) * 4;
    for (int k0 = 0; k0 < K; k0 += 16) {
        float4 av = *(const float4*)&A[(m0 + a_m)*K + k0 + a_k];
        As[a_k+0][a_m] = av.x; As[a_k+1][a_m] = av.y;
        As[a_k+2][a_m] = av.z; As[a_k+3][a_m] = av.w;
        float4 bv = make_float4(0.f,0.f,0.f,0.f);
        if (n0 + b_n < N) bv = *(const float4*)&Bw[(k0 + b_k)*N + n0 + b_n];
        *(float4*)&Bs[b_k][b_n] = bv;
        __syncthreads();
        #pragma unroll
        for (int k = 0; k < 16; ++k) {
            float4 a4 = *(const float4*)&As[k][ty*4];
            float4 b4 = *(const float4*)&Bs[k][tx*4];
            float ar[4] = {a4.x, a4.y, a4.z, a4.w};
            float br[4] = {b4.x, b4.y, b4.z, b4.w};
            #pragma unroll
            for (int i = 0; i < 4; ++i)
                #pragma unroll
                for (int j = 0; j < 4; ++j)
                    acc[i][j] += ar[i] * br[j];
        }
        __syncthreads();
    }
    #pragma unroll
    for (int i = 0; i < 4; ++i) {
        int mm = m0 + ty*4 + i;
        #pragma unroll
        for (int j = 0; j < 4; ++j) {
            int nn = n0 + tx*4 + j;
            if (nn >= N) continue;
            float v = acc[i][j];
            if (MODE == 0) {
                if (nn < DI)            g_z[mm*DI + nn] = v;
                else if (nn < DI + CD)  g_xbc[mm*CD + nn - DI] = v;
                else {
                    int h = nn - DI - CD;
                    float t  = v + dt_bias[h];
                    float sp = (t > 20.f) ? t : log1pf(expf(t));
                    g_dt[mm*H_ + h] = sp;
                    g_dA[mm*H_ + h] = expf(sp * (-expf(A_log[h])));
                }
            } else {
                g_t1[mm*DM + nn] = v;
            }
        }
    }
}

// ------------------------- kernel 3: depthwise causal conv + SiLU ---------
__global__ void __launch_bounds__(256)
dwconv_kernel(const float* __restrict__ w,
              const float* __restrict__ bias) {
    int idx = blockIdx.x*256 + threadIdx.x;
    if (idx >= B_*L_*CD) return;
    int c = idx % CD;
    int m = idx / CD;          // b*L + l
    int l = m % L_;
    float acc = bias[c];
    #pragma unroll
    for (int k = 0; k < 4; ++k) {
        int l2 = l + k - 3;
        if (l2 >= 0) acc += g_xbc[(m - 3 + k)*CD + c] * w[c*4 + k];
    }
    float s = 1.f / (1.f + expf(-acc));
    g_xbc2[idx] = acc * s;
}

// ------------------------- scan phase A: per-chunk local scan from zero ---
// thread = (b, h, chunk, n); 3 p-states in registers.
__global__ void __launch_bounds__(256)
scanA_kernel() {
    int idx = blockIdx.x*256 + threadIdx.x;
    int n = idx & 15;
    int c = (idx >> 4) & 15;
    int h = (idx >> 8) & 255;
    int b = idx >> 16;
    float s0 = 0.f, s1 = 0.f, s2 = 0.f, pr = 1.f;
    int mBase = b*L_ + c*CHUNK;
    for (int t = 0; t < CHUNK; ++t) {
        int m = mBase + t;
        float dA  = g_dA[m*H_ + h];
        float dtv = g_dt[m*H_ + h];
        const float* xb = &g_xbc2[m*CD];
        float w  = dtv * xb[DI + n];        // dt * B_n
        float x0 = xb[h*3+0], x1 = xb[h*3+1], x2 = xb[h*3+2];
        s0 = s0*dA + w*x0;
        s1 = s1*dA + w*x1;
        s2 = s2*dA + w*x2;
        pr *= dA;
    }
    int u = (b*H_ + h)*NC + c;
    g_cs[u*48 +      n] = s0;
    g_cs[u*48 + 16 + n] = s1;
    g_cs[u*48 + 32 + n] = s2;
    if (n == 0) g_cp[u] = pr;
}

// ------------------------- scan phase B: inter-chunk combine --------------
// h_start[c] = carry;  carry = carry * P[c] + S[c]   (exact)
__global__ void __launch_bounds__(256)
scanB_kernel() {
    int idx = blockIdx.x*256 + threadIdx.x;
    int n = idx & 15;
    int h = (idx >> 4) & 255;
    int b = idx >> 12;
    float c0 = 0.f, c1 = 0.f, c2 = 0.f;
    for (int c = 0; c < NC; ++c) {
        int u = (b*H_ + h)*NC + c;
        g_hs[u*48 +      n] = c0;
        g_hs[u*48 + 16 + n] = c1;
        g_hs[u*48 + 32 + n] = c2;
        float pr = g_cp[u];
        c0 = c0*pr + g_cs[u*48 +      n];
        c1 = c1*pr + g_cs[u*48 + 16 + n];
        c2 = c2*pr + g_cs[u*48 + 32 + n];
    }
}

// ------------------------- scan phase C: re-scan with true init, emit y ---
__global__ void __launch_bounds__(256)
scanC_kernel(const float* __restrict__ Dp) {
    int idx = blockIdx.x*256 + threadIdx.x;
    int n = idx & 15;
    int c = (idx >> 4) & 15;
    int h = (idx >> 8) & 255;
    int b = idx >> 16;
    int u = (b*H_ + h)*NC + c;
    float s0 = g_hs[u*48 + n];
    float s1 = g_hs[u*48 + 16 + n];
    float s2 = g_hs[u*48 + 32 + n];
    float Dh = Dp[h];
    int mBase = b*L_ + c*CHUNK;
    for (int t = 0; t < CHUNK; ++t) {
        int m = mBase + t;
        float dA  = g_dA[m*H_ + h];
        float dtv = g_dt[m*H_ + h];
        const float* xb = &g_xbc2[m*CD];
        float w  = dtv * xb[DI + n];
        float x0 = xb[h*3+0], x1 = xb[h*3+1], x2 = xb[h*3+2];
        s0 = s0*dA + w*x0;
        s1 = s1*dA + w*x1;
        s2 = s2*dA + w*x2;
        float Cn = xb[DI + NS + n];
        float y0 = s0*Cn, y1 = s1*Cn, y2 = s2*Cn;
        #pragma unroll
        for (int off = 8; off >= 1; off >>= 1) {
            y0 += __shfl_xor_sync(0xffffffffu, y0, off);
            y1 += __shfl_xor_sync(0xffffffffu, y1, off);
            y2 += __shfl_xor_sync(0xffffffffu, y2, off);
        }
        if (n == 0) {
            float* yo = &g_y[m*DI + h*3];
            yo[0] = y0 + Dh*x0;
            yo[1] = y1 + Dh*x1;
            yo[2] = y2 + Dh*x2;
        }
    }
}

// ------------------------- kernel 5: gate (silu(z)) + RMSNorm -------------
__global__ void __launch_bounds__(256)
gate_norm_kernel(const float* __restrict__ nw) {
    int m = blockIdx.x;       // b*L + l
    int tid = threadIdx.x;    // 256 threads, 3 elems each
    __shared__ float red[8];
    float yv[3];
    float acc = 0.f;
    #pragma unroll
    for (int j = 0; j < 3; ++j) {
        int e = tid*3 + j;
        float y = g_y[m*DI + e];
        float z = g_z[m*DI + e];
        float g = y * (z / (1.f + expf(-z)));
        yv[j] = g;
        acc += g*g;
    }
    #pragma unroll
    for (int off = 16; off >= 1; off >>= 1)
        acc += __shfl_xor_sync(0xffffffffu, acc, off);
    if ((tid & 31) == 0) red[tid >> 5] = acc;
    __syncthreads();
    if (tid == 0) {
        float t = 0.f;
        #pragma unroll
        for (int i = 0; i < 8; ++i) t += red[i];
        red[0] = rsqrtf(t / (float)DI + 1e-5f);
    }
    __syncthreads();
    float scale = red[0];
    #pragma unroll
    for (int j = 0; j < 3; ++j) {
        int e = tid*3 + j;
        g_y[m*DI + e] = yv[j] * scale * nw[e];
    }
}

// ------------------------- kernel 7: output conv (K=4, pad (1,2)) ---------
// out[b][o][l] = sum_{c,k} t1[b][l+k-1][c] * w[o][c][k]
__global__ void __launch_bounds__(128)
conv_out_kernel(const float* __restrict__ w,
                float* __restrict__ out) {
    __shared__ float ts[35][DM];       // 35.8 KB
    int b  = blockIdx.y;
    int l0 = blockIdx.x * 32;
    int tid = threadIdx.x;             // 128 threads = 128 out channels
    for (int i = tid; i < 35*DM; i += 128) {
        int r = i / DM, cc = i % DM;
        int l = l0 - 1 + r;
        ts[r][cc] = (l >= 0 && l < L_) ? g_t1[(b*L_ + l)*DM + cc] : 0.f;
    }
    __syncthreads();
    int o = tid;
    for (int g = 0; g < 4; ++g) {
        int s0 = g*8;
        float acc[8] = {};
        for (int cc = 0; cc < DM; ++cc) {
            float4 w4 = *(const float4*)&w[(o*DM + cc)*4];
            float xv[11];
            #pragma unroll
            for (int j = 0; j < 11; ++j) xv[j] = ts[s0 + j][cc];
            #pragma unroll
            for (int s = 0; s < 8; ++s)
                acc[s] += w4.x*xv[s] + w4.y*xv[s+1] + w4.z*xv[s+2] + w4.w*xv[s+3];
        }
        #pragma unroll
        for (int s = 0; s < 8; ++s)
            out[(b*OC + o)*L_ + l0 + s0 + s] = acc[s];
    }
}

// ------------------------- launch ----------------------------------------
extern "C" void kernel_launch(void* const* d_in, const int* in_sizes, int n_in,
                              void* d_out, int out_size) {
    const float* x           = (const float*)d_in[0];
    const float* conv_w      = (const float*)d_in[1];
    const float* conv_b      = (const float*)d_in[2];
    const float* in_proj_w   = (const float*)d_in[3];
    const float* dw_conv_w   = (const float*)d_in[4];
    const float* dw_conv_b   = (const float*)d_in[5];
    const float* dt_bias     = (const float*)d_in[6];
    const float* A_log       = (const float*)d_in[7];
    const float* Dp          = (const float*)d_in[8];
    const float* norm_w      = (const float*)d_in[9];
    const float* mamba_out_w = (const float*)d_in[10];
    const float* out_conv_w  = (const float*)d_in[11];
    float* out = (float*)d_out;

    conv_in_kernel<<<dim3(L_/32, B_), 256>>>(x, conv_w, conv_b);

    // in_proj: M=8192, N=1824, K=256
    gemm_kernel<0><<<dim3((DIP + 63)/64, (B_*L_)/64), 256>>>(
        in_proj_w, B_*L_, DIP, DM, dt_bias, A_log);

    dwconv_kernel<<<(B_*L_*CD + 255)/256, 256>>>(dw_conv_w, dw_conv_b);

    scanA_kernel<<<(B_*H_*NC*NS)/256, 256>>>();
    scanB_kernel<<<(B_*H_*NS)/256, 256>>>();
    scanC_kernel<<<(B_*H_*NC*NS)/256, 256>>>(Dp);

    gate_norm_kernel<<<B_*L_, 256>>>(norm_w);

    // out_proj: M=8192, N=256, K=768
    gemm_kernel<1><<<dim3(DM/64, (B_*L_)/64), 256>>>(
        mamba_out_w, B_*L_, DM, DI, nullptr, nullptr);

    conv_out_kernel<<<dim3(L_/32, B_), 128>>>(out_conv_w, out);
}

// round 7
// speedup vs baseline: 1.1620x; 1.1620x over previous
#include <cuda_runtime.h>
#include <cuda_bf16.h>
#include <math.h>

// Problem constants
#define B_    4
#define L_    2048
#define DM    256     // d_model
#define DI    768     // d_inner
#define H_    256     // nheads
#define NS    16      // d_state
#define CD    800     // conv_dim = DI + 2*NS
#define DIP   1824    // d_in_proj
#define INC   128     // input channels
#define OC    128     // output channels
#define NC    16      // scan chunks
#define CHUNK 128     // L per chunk
#define M_    (B_*L_) // 8192 rows
#define NP0   1920    // padded N for gemm0 (15 * 128)
#define KB0   16      // 256/16
#define KB1   48      // 768/16

// ------------------------- scratch (device globals) -----------------------
__device__ float  g_u   [M_*DM];        // conv_in output [m][c]
__device__ float  g_z   [M_*DI];        // gate branch
__device__ float  g_xbc [M_*CD];        // pre-dwconv
__device__ float  g_y   [M_*DI];        // scan output
__device__ float  g_t1  [M_*DM];        // out-proj result
__device__ float2 g_dadt[M_*H_];        // (softplus dt, exp(dt*A))
__device__ float4 g_xp4 [M_*H_];        // x padded: [m][h] -> (x0,x1,x2,unused)
__device__ float  g_bc  [M_*32];        // [m][0:16]=B, [16:32]=C
__device__ float  g_cs  [B_*H_*NC*3*NS];
__device__ float  g_hs  [B_*H_*NC*3*NS];
__device__ float  g_cp  [B_*H_*NC];
// bf16-split packed operands: per (kblk,row): 4 x uint4 (16B blocks of
// [hi pair(2t,2t+1) | hi pair(2t+8,2t+9) | lo pair | lo pair])
__device__ uint4  gA0p[KB0*M_*4];       // in_proj A (from g_u)       8.4 MB
__device__ uint4  gW0p[KB0*NP0*4];      // in_proj W packed            2.0 MB
__device__ uint4  gYp [KB1*M_*4];       // out_proj A (from y)        25.2 MB
__device__ uint4  gW1p[KB1*DM*4];       // out_proj W packed           0.8 MB

// ------------------------- bf16 split helpers -----------------------------
__device__ __forceinline__ void split2(float a, float b, unsigned &hw, unsigned &lw) {
    __nv_bfloat16 ah = __float2bfloat16(a);
    __nv_bfloat16 bh = __float2bfloat16(b);
    float ar = a - __bfloat162float(ah);
    float br = b - __bfloat162float(bh);
    __nv_bfloat16 al = __float2bfloat16(ar);
    __nv_bfloat16 bl = __float2bfloat16(br);
    hw = ((unsigned)__bfloat16_as_ushort(bh) << 16) | (unsigned)__bfloat16_as_ushort(ah);
    lw = ((unsigned)__bfloat16_as_ushort(bl) << 16) | (unsigned)__bfloat16_as_ushort(al);
}
__device__ __forceinline__ void pack_block16(const float* v, uint4* dst) {
    #pragma unroll
    for (int t = 0; t < 4; ++t) {
        unsigned h0, l0, h1, l1;
        split2(v[2*t],     v[2*t + 1], h0, l0);
        split2(v[2*t + 8], v[2*t + 9], h1, l1);
        dst[t] = make_uint4(h0, h1, l0, l1);
    }
}

// ------------------------- pack kernels ------------------------------------
__global__ void __launch_bounds__(256) pack_A0_kernel() {
    int idx = blockIdx.x*256 + threadIdx.x;       // kb*M + m
    int kb = idx >> 13, m = idx & (M_ - 1);
    float v[16];
    #pragma unroll
    for (int r = 0; r < 16; ++r) v[r] = g_u[m*DM + kb*16 + r];
    pack_block16(v, &gA0p[(size_t)idx*4]);
}
__global__ void __launch_bounds__(256)
pack_W_kernel(const float* __restrict__ W, uint4* __restrict__ dst,
              int Nsrc, int NPad, int total) {
    int idx = blockIdx.x*256 + threadIdx.x;       // kb*NPad + n
    if (idx >= total) return;
    int kb = idx / NPad, n = idx % NPad;
    float v[16];
    #pragma unroll
    for (int r = 0; r < 16; ++r)
        v[r] = (n < Nsrc) ? W[(kb*16 + r)*Nsrc + n] : 0.f;
    pack_block16(v, &dst[(size_t)idx*4]);
}

// ------------------------- kernel 1: input conv (K=4, pad (1,2)) ----------
__global__ void __launch_bounds__(256)
conv_in_kernel(const float* __restrict__ x, const float* __restrict__ w,
               const float* __restrict__ bias) {
    __shared__ float xs[INC][36];
    int b  = blockIdx.y;
    int l0 = blockIdx.x * 32;
    int tid = threadIdx.x;
    for (int i = tid; i < INC*35; i += 256) {
        int ci = i / 35, j = i % 35;
        int l = l0 - 1 + j;
        xs[ci][j] = (l >= 0 && l < L_) ? x[(b*INC + ci)*L_ + l] : 0.f;
    }
    __syncthreads();
    int co = tid;
    float bc = bias[co];
    for (int g = 0; g < 4; ++g) {
        int s0 = g * 8;
        float acc[8];
        #pragma unroll
        for (int s = 0; s < 8; ++s) acc[s] = bc;
        for (int ci = 0; ci < INC; ++ci) {
            float4 w4 = *(const float4*)&w[(co*INC + ci)*4];
            float xv[11];
            #pragma unroll
            for (int j = 0; j < 11; ++j) xv[j] = xs[ci][s0 + j];
            #pragma unroll
            for (int s = 0; s < 8; ++s)
                acc[s] += w4.x*xv[s] + w4.y*xv[s+1] + w4.z*xv[s+2] + w4.w*xv[s+3];
        }
        #pragma unroll
        for (int s = 0; s < 8; ++s)
            g_u[(b*L_ + l0 + s0 + s)*DM + co] = acc[s];
    }
}

// ------------------------- HMMA GEMM (bf16 3-term split, fp32 acc) --------
#define MMA_B16(d, a0,a1,a2,a3, b0,b1) \
    asm volatile("mma.sync.aligned.m16n8k16.row.col.f32.bf16.bf16.f32 " \
        "{%0,%1,%2,%3}, {%4,%5,%6,%7}, {%8,%9}, {%0,%1,%2,%3};" \
        : "+f"(d[0]), "+f"(d[1]), "+f"(d[2]), "+f"(d[3]) \
        : "r"(a0), "r"(a1), "r"(a2), "r"(a3), "r"(b0), "r"(b1))
#define CPA16(s, g) asm volatile("cp.async.cg.shared.global [%0], [%1], 16;" :: "r"(s), "l"(g))
#define CPCOMMIT()  asm volatile("cp.async.commit_group;")
#define CPWAIT()    asm volatile("cp.async.wait_group 0;")

// 128x128 CTA tile, 8 warps (4m x 2n), warp tile 32x64, K-step 16.
// MODE 0: epilogue splits z / xbc / dt(softplus)+dA.  MODE 1: store g_t1.
template<int MODE>
__global__ void __launch_bounds__(256)
hgemm_kernel(const uint4* __restrict__ Ap, const uint4* __restrict__ Bp,
             int NPad, int N, int KB,
             const float* __restrict__ dt_bias, const float* __restrict__ A_log) {
    __shared__ uint4 sb[2][1024];   // [buf][ As:512 | Bs:512 ]
    int tid  = threadIdx.x;
    int m0   = blockIdx.y * 128, n0 = blockIdx.x * 128;
    int lane = tid & 31, warp = tid >> 5;
    int g = lane >> 2, t = lane & 3;
    int wm = (warp >> 1) * 32, wn = (warp & 1) * 64;

    int crow = tid >> 1;            // 0..127
    int coff = (tid & 1) * 2;       // uint4 offset in 4-wide row

    float acc[2][8][4];
    #pragma unroll
    for (int mi = 0; mi < 2; ++mi)
        #pragma unroll
        for (int j = 0; j < 8; ++j)
            #pragma unroll
            for (int d = 0; d < 4; ++d) acc[mi][j][d] = 0.f;

    auto copy_tile = [&](int kb, int buf) {
        const uint4* asrc = Ap + ((size_t)kb*M_  + m0 + crow)*4 + coff;
        const uint4* bsrc = Bp + ((size_t)kb*NPad + n0 + crow)*4 + coff;
        unsigned sa = (unsigned)__cvta_generic_to_shared(&sb[buf][crow*4 + coff]);
        unsigned sB = (unsigned)__cvta_generic_to_shared(&sb[buf][512 + crow*4 + coff]);
        CPA16(sa,      asrc);
        CPA16(sa + 16, asrc + 1);
        CPA16(sB,      bsrc);
        CPA16(sB + 16, bsrc + 1);
    };

    copy_tile(0, 0); CPCOMMIT(); CPWAIT(); __syncthreads();
    int p = 0;
    for (int kb = 0; kb < KB; ++kb) {
        if (kb + 1 < KB) { copy_tile(kb + 1, p ^ 1); CPCOMMIT(); }
        const uint4* As = sb[p];
        const uint4* Bs = sb[p] + 512;
        unsigned a[2][8];
        #pragma unroll
        for (int mi = 0; mi < 2; ++mi) {
            uint4 v0 = As[(wm + 16*mi + g)*4 + t];
            uint4 v1 = As[(wm + 16*mi + g + 8)*4 + t];
            a[mi][0] = v0.x; a[mi][2] = v0.y; a[mi][4] = v0.z; a[mi][6] = v0.w;
            a[mi][1] = v1.x; a[mi][3] = v1.y; a[mi][5] = v1.z; a[mi][7] = v1.w;
        }
        #pragma unroll
        for (int j = 0; j < 8; ++j) {
            uint4 bv = Bs[(wn + 8*j + g)*4 + t];
            #pragma unroll
            for (int mi = 0; mi < 2; ++mi) {
                MMA_B16(acc[mi][j], a[mi][0], a[mi][1], a[mi][2], a[mi][3], bv.x, bv.y); // Ah*Bh
                MMA_B16(acc[mi][j], a[mi][0], a[mi][1], a[mi][2], a[mi][3], bv.z, bv.w); // Ah*Bl
                MMA_B16(acc[mi][j], a[mi][4], a[mi][5], a[mi][6], a[mi][7], bv.x, bv.y); // Al*Bh
            }
        }
        if (kb + 1 < KB) CPWAIT();
        __syncthreads();
        p ^= 1;
    }

    #pragma unroll
    for (int mi = 0; mi < 2; ++mi)
        #pragma unroll
        for (int j = 0; j < 8; ++j)
            #pragma unroll
            for (int d = 0; d < 4; ++d) {
                int mm = m0 + wm + 16*mi + g + ((d >= 2) ? 8 : 0);
                int nn = n0 + wn + 8*j + 2*t + (d & 1);
                if (nn >= N) continue;
                float v = acc[mi][j][d];
                if (MODE == 0) {
                    if (nn < DI)           g_z[mm*DI + nn] = v;
                    else if (nn < DI + CD) g_xbc[mm*CD + nn - DI] = v;
                    else {
                        int h = nn - DI - CD;
                        float tt = v + dt_bias[h];
                        float sp = (tt > 20.f) ? tt : log1pf(expf(tt));
                        g_dadt[mm*H_ + h] = make_float2(sp, expf(sp * (-expf(A_log[h]))));
                    }
                } else {
                    g_t1[mm*DM + nn] = v;
                }
            }
}

// ------------------------- depthwise causal conv + SiLU -------------------
__global__ void __launch_bounds__(256)
dwconv_kernel(const float* __restrict__ w, const float* __restrict__ bias) {
    int idx = blockIdx.x*256 + threadIdx.x;
    if (idx >= B_*L_*CD) return;
    int c = idx % CD;
    int m = idx / CD;
    int l = m % L_;
    float acc = bias[c];
    #pragma unroll
    for (int k = 0; k < 4; ++k) {
        int l2 = l + k - 3;
        if (l2 >= 0) acc += g_xbc[(m - 3 + k)*CD + c] * w[c*4 + k];
    }
    float s = 1.f / (1.f + expf(-acc));
    float val = acc * s;
    if (c < DI) {
        int h = c / 3, pp = c - h*3;
        ((float*)&g_xp4[m*H_ + h])[pp] = val;
    } else {
        g_bc[m*32 + (c - DI)] = val;
    }
}

// ------------------------- scan phase A -----------------------------------
__global__ void __launch_bounds__(256) scanA_kernel() {
    int idx = blockIdx.x*256 + threadIdx.x;
    int n = idx & 15;
    int c = (idx >> 4) & 15;
    int h = (idx >> 8) & 255;
    int b = idx >> 16;
    float s0 = 0.f, s1 = 0.f, s2 = 0.f, pr = 1.f;
    int mBase = b*L_ + c*CHUNK;
    for (int t = 0; t < CHUNK; ++t) {
        int m = mBase + t;
        float2 dd = g_dadt[m*H_ + h];        // (dt, dA)
        float4 xp = g_xp4[m*H_ + h];
        float Bn  = g_bc[m*32 + n];
        float w = dd.x * Bn;
        s0 = s0*dd.y + w*xp.x;
        s1 = s1*dd.y + w*xp.y;
        s2 = s2*dd.y + w*xp.z;
        pr *= dd.y;
    }
    int u = (b*H_ + h)*NC + c;
    g_cs[u*48 +      n] = s0;
    g_cs[u*48 + 16 + n] = s1;
    g_cs[u*48 + 32 + n] = s2;
    if (n == 0) g_cp[u] = pr;
}

// ------------------------- scan phase B -----------------------------------
__global__ void __launch_bounds__(256) scanB_kernel() {
    int idx = blockIdx.x*256 + threadIdx.x;
    int n = idx & 15;
    int h = (idx >> 4) & 255;
    int b = idx >> 12;
    float c0 = 0.f, c1 = 0.f, c2 = 0.f;
    for (int c = 0; c < NC; ++c) {
        int u = (b*H_ + h)*NC + c;
        g_hs[u*48 +      n] = c0;
        g_hs[u*48 + 16 + n] = c1;
        g_hs[u*48 + 32 + n] = c2;
        float pr = g_cp[u];
        c0 = c0*pr + g_cs[u*48 +      n];
        c1 = c1*pr + g_cs[u*48 + 16 + n];
        c2 = c2*pr + g_cs[u*48 + 32 + n];
    }
}

// ------------------------- scan phase C -----------------------------------
__global__ void __launch_bounds__(256) scanC_kernel(const float* __restrict__ Dp) {
    int idx = blockIdx.x*256 + threadIdx.x;
    int n = idx & 15;
    int c = (idx >> 4) & 15;
    int h = (idx >> 8) & 255;
    int b = idx >> 16;
    int u = (b*H_ + h)*NC + c;
    float s0 = g_hs[u*48 + n];
    float s1 = g_hs[u*48 + 16 + n];
    float s2 = g_hs[u*48 + 32 + n];
    float Dh = Dp[h];
    int mBase = b*L_ + c*CHUNK;
    for (int t = 0; t < CHUNK; ++t) {
        int m = mBase + t;
        float2 dd = g_dadt[m*H_ + h];
        float4 xp = g_xp4[m*H_ + h];
        float Bn  = g_bc[m*32 + n];
        float Cn  = g_bc[m*32 + 16 + n];
        float w = dd.x * Bn;
        s0 = s0*dd.y + w*xp.x;
        s1 = s1*dd.y + w*xp.y;
        s2 = s2*dd.y + w*xp.z;
        float y0 = s0*Cn, y1 = s1*Cn, y2 = s2*Cn;
        #pragma unroll
        for (int off = 8; off >= 1; off >>= 1) {
            y0 += __shfl_xor_sync(0xffffffffu, y0, off);
            y1 += __shfl_xor_sync(0xffffffffu, y1, off);
            y2 += __shfl_xor_sync(0xffffffffu, y2, off);
        }
        if (n == 0) {
            float* yo = &g_y[m*DI + h*3];
            yo[0] = y0 + Dh*xp.x;
            yo[1] = y1 + Dh*xp.y;
            yo[2] = y2 + Dh*xp.z;
        }
    }
}

// ------------------------- gate + RMSNorm + pack for gemm1 ----------------
__global__ void __launch_bounds__(256)
gate_norm_kernel(const float* __restrict__ nw) {
    int m = blockIdx.x;
    int tid = threadIdx.x;
    __shared__ float red[8];
    __shared__ float ys[DI];
    float yv[3];
    float acc = 0.f;
    #pragma unroll
    for (int j = 0; j < 3; ++j) {
        int e = tid*3 + j;
        float y = g_y[m*DI + e];
        float z = g_z[m*DI + e];
        float gg = y * (z / (1.f + expf(-z)));
        yv[j] = gg;
        acc += gg*gg;
    }
    #pragma unroll
    for (int off = 16; off >= 1; off >>= 1)
        acc += __shfl_xor_sync(0xffffffffu, acc, off);
    if ((tid & 31) == 0) red[tid >> 5] = acc;
    __syncthreads();
    if (tid == 0) {
        float t = 0.f;
        #pragma unroll
        for (int i = 0; i < 8; ++i) t += red[i];
        red[0] = rsqrtf(t / (float)DI + 1e-5f);
    }
    __syncthreads();
    float scale = red[0];
    #pragma unroll
    for (int j = 0; j < 3; ++j) {
        int e = tid*3 + j;
        ys[e] = yv[j] * scale * nw[e];
    }
    __syncthreads();
    if (tid < KB1) {                       // 48 k-blocks of 16
        float v[16];
        #pragma unroll
        for (int r = 0; r < 16; ++r) v[r] = ys[tid*16 + r];
        pack_block16(v, &gYp[((size_t)tid*M_ + m)*4]);
    }
}

// ------------------------- output conv (K=4, pad (1,2)) -------------------
__global__ void __launch_bounds__(128)
conv_out_kernel(const float* __restrict__ w, float* __restrict__ out) {
    __shared__ float ts[35][DM];
    int b  = blockIdx.y;
    int l0 = blockIdx.x * 32;
    int tid = threadIdx.x;
    for (int i = tid; i < 35*DM; i += 128) {
        int r = i / DM, cc = i % DM;
        int l = l0 - 1 + r;
        ts[r][cc] = (l >= 0 && l < L_) ? g_t1[(b*L_ + l)*DM + cc] : 0.f;
    }
    __syncthreads();
    int o = tid;
    for (int g = 0; g < 4; ++g) {
        int s0 = g*8;
        float acc[8] = {};
        for (int cc = 0; cc < DM; ++cc) {
            float4 w4 = *(const float4*)&w[(o*DM + cc)*4];
            float xv[11];
            #pragma unroll
            for (int j = 0; j < 11; ++j) xv[j] = ts[s0 + j][cc];
            #pragma unroll
            for (int s = 0; s < 8; ++s)
                acc[s] += w4.x*xv[s] + w4.y*xv[s+1] + w4.z*xv[s+2] + w4.w*xv[s+3];
        }
        #pragma unroll
        for (int s = 0; s < 8; ++s)
            out[(b*OC + o)*L_ + l0 + s0 + s] = acc[s];
    }
}

// ------------------------- launch ----------------------------------------
extern "C" void kernel_launch(void* const* d_in, const int* in_sizes, int n_in,
                              void* d_out, int out_size) {
    const float* x           = (const float*)d_in[0];
    const float* conv_w      = (const float*)d_in[1];
    const float* conv_b      = (const float*)d_in[2];
    const float* in_proj_w   = (const float*)d_in[3];
    const float* dw_conv_w   = (const float*)d_in[4];
    const float* dw_conv_b   = (const float*)d_in[5];
    const float* dt_bias     = (const float*)d_in[6];
    const float* A_log       = (const float*)d_in[7];
    const float* Dp          = (const float*)d_in[8];
    const float* norm_w      = (const float*)d_in[9];
    const float* mamba_out_w = (const float*)d_in[10];
    const float* out_conv_w  = (const float*)d_in[11];
    float* out = (float*)d_out;

    uint4 *pW0, *pW1, *pA0, *pY;
    cudaGetSymbolAddress((void**)&pW0, gW0p);
    cudaGetSymbolAddress((void**)&pW1, gW1p);
    cudaGetSymbolAddress((void**)&pA0, gA0p);
    cudaGetSymbolAddress((void**)&pY,  gYp);

    // weight packs (independent of data path)
    pack_W_kernel<<<(KB0*NP0 + 255)/256, 256>>>(in_proj_w,   pW0, DIP, NP0, KB0*NP0);
    pack_W_kernel<<<(KB1*DM + 255)/256, 256>>>(mamba_out_w, pW1, DM,  DM,  KB1*DM);

    conv_in_kernel<<<dim3(L_/32, B_), 256>>>(x, conv_w, conv_b);
    pack_A0_kernel<<<(KB0*M_)/256, 256>>>();

    // in_proj: M=8192, N=1824 (pad 1920), K=256
    hgemm_kernel<0><<<dim3(NP0/128, M_/128), 256>>>(pA0, pW0, NP0, DIP, KB0,
                                                    dt_bias, A_log);

    dwconv_kernel<<<(B_*L_*CD + 255)/256, 256>>>(dw_conv_w, dw_conv_b);

    scanA_kernel<<<(B_*H_*NC*NS)/256, 256>>>();
    scanB_kernel<<<(B_*H_*NS)/256, 256>>>();
    scanC_kernel<<<(B_*H_*NC*NS)/256, 256>>>(Dp);

    gate_norm_kernel<<<M_, 256>>>(norm_w);

    // out_proj: M=8192, N=256, K=768
    hgemm_kernel<1><<<dim3(DM/128, M_/128), 256>>>(pY, pW1, DM, DM, KB1,
                                                   nullptr, nullptr);

    conv_out_kernel<<<dim3(L_/32, B_), 128>>>(out_conv_w, out);
}

// round 9
// speedup vs baseline: 1.8047x; 1.5531x over previous
#include <cuda_runtime.h>
#include <cuda_bf16.h>
#include <math.h>

// Problem constants
#define B_    4
#define L_    2048
#define DM    256     // d_model
#define DI    768     // d_inner
#define H_    256     // nheads
#define NS    16      // d_state
#define CD    800     // conv_dim = DI + 2*NS
#define DIP   1824    // d_in_proj
#define INC   128     // input channels
#define OC    128     // output channels
#define NC    16      // scan chunks
#define CHUNK 128     // L per chunk
#define M_    (B_*L_) // 8192 rows
#define NP0   1920    // padded N for gemm0 (15 * 128)
#define KB0   16      // 256/16 (in_proj K blocks)
#define KB1   48      // 768/16 (out_proj K blocks)
#define KBX   8       // 128/16 (x channels K blocks, per tap)
#define KBT   16      // 256/16 (t1 channels K blocks, per tap)

// ------------------------- scratch (device globals) -----------------------
__device__ float  g_u   [M_*DM];        // conv_in output [m][c]
__device__ float  g_z   [M_*DI];        // gate branch
__device__ float  g_xbc [M_*CD];        // pre-dwconv
__device__ float  g_y   [M_*DI];        // scan output
__device__ float  g_t1  [M_*DM];        // out-proj result
__device__ float2 g_dadt[M_*H_];        // (softplus dt, exp(dt*A))
__device__ float4 g_xp4 [M_*H_];        // x padded: [m][h] -> (x0,x1,x2,unused)
__device__ float  g_bc  [M_*32];        // [m][0:16]=B, [16:32]=C
__device__ float  g_cs  [B_*H_*NC*3*NS];
__device__ float  g_hs  [B_*H_*NC*3*NS];
__device__ float  g_cp  [B_*H_*NC];
// bf16-split packed operands: per (kblk,row): 4 x uint4 of
// [hi pair(2t,2t+1) | hi pair(2t+8,2t+9) | lo pair | lo pair]
__device__ uint4  gA0p[KB0*M_*4];       // in_proj A (from g_u)
__device__ uint4  gW0p[KB0*NP0*4];      // in_proj W packed
__device__ uint4  gYp [KB1*M_*4];       // out_proj A (from y)
__device__ uint4  gW1p[KB1*DM*4];       // out_proj W packed
__device__ uint4  gXp [KBX*M_*4];       // x transposed+packed [kb][m]
__device__ uint4  gWcp[4*KBX*DM*4];     // conv_in W packed, kb_eff = tap*8+kbx
__device__ uint4  gT1p[KBT*M_*4];       // t1 packed
__device__ uint4  gWop[4*KBT*OC*4];     // conv_out W packed
__device__ uint4  g_zero4[4];           // static zeros for invalid conv rows

// ------------------------- bf16 split helpers -----------------------------
__device__ __forceinline__ void split2(float a, float b, unsigned &hw, unsigned &lw) {
    __nv_bfloat16 ah = __float2bfloat16(a);
    __nv_bfloat16 bh = __float2bfloat16(b);
    float ar = a - __bfloat162float(ah);
    float br = b - __bfloat162float(bh);
    __nv_bfloat16 al = __float2bfloat16(ar);
    __nv_bfloat16 bl = __float2bfloat16(br);
    hw = ((unsigned)__bfloat16_as_ushort(bh) << 16) | (unsigned)__bfloat16_as_ushort(ah);
    lw = ((unsigned)__bfloat16_as_ushort(bl) << 16) | (unsigned)__bfloat16_as_ushort(al);
}
__device__ __forceinline__ void pack_block16(const float* v, uint4* dst) {
    #pragma unroll
    for (int t = 0; t < 4; ++t) {
        unsigned h0, l0, h1, l1;
        split2(v[2*t],     v[2*t + 1], h0, l0);
        split2(v[2*t + 8], v[2*t + 9], h1, l1);
        dst[t] = make_uint4(h0, h1, l0, l1);
    }
}

// ------------------------- pack kernels ------------------------------------
__global__ void __launch_bounds__(256) pack_A0_kernel() {
    int idx = blockIdx.x*256 + threadIdx.x;       // kb*M + m
    int kb = idx >> 13, m = idx & (M_ - 1);
    float v[16];
    #pragma unroll
    for (int r = 0; r < 16; ++r) v[r] = g_u[m*DM + kb*16 + r];
    pack_block16(v, &gA0p[(size_t)idx*4]);
}
__global__ void __launch_bounds__(256) pack_T1_kernel() {
    int idx = blockIdx.x*256 + threadIdx.x;       // kb*M + m
    int kb = idx >> 13, m = idx & (M_ - 1);
    float v[16];
    #pragma unroll
    for (int r = 0; r < 16; ++r) v[r] = g_t1[m*DM + kb*16 + r];
    pack_block16(v, &gT1p[(size_t)idx*4]);
}
__global__ void __launch_bounds__(256) pack_X_kernel(const float* __restrict__ x) {
    int idx = blockIdx.x*256 + threadIdx.x;       // kb*M + m, kb 0..7
    int kb = idx >> 13, m = idx & (M_ - 1);
    int b = m >> 11, l = m & 2047;
    float v[16];
    #pragma unroll
    for (int r = 0; r < 16; ++r) v[r] = x[(b*INC + kb*16 + r)*L_ + l];
    pack_block16(v, &gXp[(size_t)idx*4]);
}
__global__ void __launch_bounds__(256)
pack_W_kernel(const float* __restrict__ W, uint4* __restrict__ dst,
              int Nsrc, int NPad, int total) {
    int idx = blockIdx.x*256 + threadIdx.x;       // kb*NPad + n
    if (idx >= total) return;
    int kb = idx / NPad, n = idx % NPad;
    float v[16];
    #pragma unroll
    for (int r = 0; r < 16; ++r)
        v[r] = (n < Nsrc) ? W[(kb*16 + r)*Nsrc + n] : 0.f;
    pack_block16(v, &dst[(size_t)idx*4]);
}
// conv_in weights: kb_eff = tap*KBX + kbx; v[r] = conv_w[co][kbx*16+r][tap]
__global__ void __launch_bounds__(256) pack_Wc_kernel(const float* __restrict__ W) {
    int idx = blockIdx.x*256 + threadIdx.x;       // kb_eff*DM + co
    int kbe = idx >> 8, co = idx & 255;
    int tap = kbe >> 3, kbx = kbe & 7;
    float v[16];
    #pragma unroll
    for (int r = 0; r < 16; ++r)
        v[r] = W[(co*INC + kbx*16 + r)*4 + tap];
    pack_block16(v, &gWcp[(size_t)idx*4]);
}
// conv_out weights: kb_eff = tap*KBT + kbx; v[r] = out_conv_w[o][kbx*16+r][tap]
__global__ void __launch_bounds__(256) pack_Wo_kernel(const float* __restrict__ W) {
    int idx = blockIdx.x*256 + threadIdx.x;       // kb_eff*OC + o
    int kbe = idx >> 7, o = idx & 127;
    int tap = kbe >> 4, kbx = kbe & 15;
    float v[16];
    #pragma unroll
    for (int r = 0; r < 16; ++r)
        v[r] = W[(o*DM + kbx*16 + r)*4 + tap];
    pack_block16(v, &gWop[(size_t)idx*4]);
}

// ------------------------- HMMA GEMM (bf16 3-term split, fp32 acc) --------
#define MMA_B16(d, a0,a1,a2,a3, b0,b1) \
    asm volatile("mma.sync.aligned.m16n8k16.row.col.f32.bf16.bf16.f32 " \
        "{%0,%1,%2,%3}, {%4,%5,%6,%7}, {%8,%9}, {%0,%1,%2,%3};" \
        : "+f"(d[0]), "+f"(d[1]), "+f"(d[2]), "+f"(d[3]) \
        : "r"(a0), "r"(a1), "r"(a2), "r"(a3), "r"(b0), "r"(b1))
#define CPA16(s, g) asm volatile("cp.async.cg.shared.global [%0], [%1], 16;" :: "r"(s), "l"(g))
#define CPCOMMIT()  asm volatile("cp.async.commit_group;")
#define CPWAIT()    asm volatile("cp.async.wait_group 0;")

// TM x 128 CTA tile, 8 warps, warp tile (TM/4)x64, K-step 16.
// CONV_KBI != 0: K blocks = 4 taps x CONV_KBI; A rows shifted by (tap-1) with
// zero-fill outside the batch's [0,L) range.
// MODE 0: in_proj epilogue (z / xbc / softplus-dt + dA)
// MODE 1: plain store g_t1
// MODE 2: conv_in: + bias, store g_u
// MODE 3: conv_out: transpose store to out[b][o][l]
template<int MODE, int TM, int CONV_KBI>
__global__ void __launch_bounds__(256)
hgemm_kernel(const uint4* __restrict__ Ap, const uint4* __restrict__ Bp,
             int NPad, int N, int KB,
             const float* __restrict__ aux1, const float* __restrict__ aux2,
             float* __restrict__ outp) {
    constexpr int ATILE = TM * 4;                 // uint4 per A tile
    constexpr int MI = TM / 64;
    __shared__ uint4 sb[2][ATILE + 512];
    int tid  = threadIdx.x;
    int m0   = blockIdx.y * TM, n0 = blockIdx.x * 128;
    int lane = tid & 31, warp = tid >> 5;
    int g = lane >> 2, t = lane & 3;
    int wm = (warp >> 1) * (TM/4), wn = (warp & 1) * 64;

    float acc[MI][8][4];
    #pragma unroll
    for (int mi = 0; mi < MI; ++mi)
        #pragma unroll
        for (int j = 0; j < 8; ++j)
            #pragma unroll
            for (int d = 0; d < 4; ++d) acc[mi][j][d] = 0.f;

    auto copy_tile = [&](int kbe, int buf) {
        int kbx = kbe, shift = 0;
        if (CONV_KBI) { kbx = kbe & (CONV_KBI-1); shift = (kbe / CONV_KBI) - 1; }
        // ---- A tile ----
        if (TM == 128) {
            int crow = tid >> 1, coff = (tid & 1) * 2;
            const uint4* asrc = Ap + ((size_t)kbx*M_ + m0 + crow + shift)*4 + coff;
            if (CONV_KBI) {
                int ld = ((m0 + crow) & (L_-1)) + shift;
                if ((unsigned)ld >= (unsigned)L_) asrc = g_zero4;
            }
            unsigned sa = (unsigned)__cvta_generic_to_shared(&sb[buf][crow*4 + coff]);
            CPA16(sa,      asrc);
            CPA16(sa + 16, asrc + 1);
        } else {
            int arow = tid >> 2, aslot = tid & 3;
            const uint4* asrc = Ap + ((size_t)kbx*M_ + m0 + arow + shift)*4 + aslot;
            if (CONV_KBI) {
                int ld = ((m0 + arow) & (L_-1)) + shift;
                if ((unsigned)ld >= (unsigned)L_) asrc = g_zero4;
            }
            unsigned sa = (unsigned)__cvta_generic_to_shared(&sb[buf][arow*4 + aslot]);
            CPA16(sa, asrc);
        }
        // ---- B tile (always 128 rows) ----
        {
            int brow = tid >> 1, bcoff = (tid & 1) * 2;
            const uint4* bsrc = Bp + ((size_t)kbe*NPad + n0 + brow)*4 + bcoff;
            unsigned sB = (unsigned)__cvta_generic_to_shared(&sb[buf][ATILE + brow*4 + bcoff]);
            CPA16(sB,      bsrc);
            CPA16(sB + 16, bsrc + 1);
        }
    };

    copy_tile(0, 0); CPCOMMIT(); CPWAIT(); __syncthreads();
    int p = 0;
    for (int kb = 0; kb < KB; ++kb) {
        if (kb + 1 < KB) { copy_tile(kb + 1, p ^ 1); CPCOMMIT(); }
        const uint4* As = sb[p];
        const uint4* Bs = sb[p] + ATILE;
        unsigned a[MI][8];
        #pragma unroll
        for (int mi = 0; mi < MI; ++mi) {
            uint4 v0 = As[(wm + 16*mi + g)*4 + t];
            uint4 v1 = As[(wm + 16*mi + g + 8)*4 + t];
            a[mi][0] = v0.x; a[mi][2] = v0.y; a[mi][4] = v0.z; a[mi][6] = v0.w;
            a[mi][1] = v1.x; a[mi][3] = v1.y; a[mi][5] = v1.z; a[mi][7] = v1.w;
        }
        #pragma unroll
        for (int j = 0; j < 8; ++j) {
            uint4 bv = Bs[(wn + 8*j + g)*4 + t];
            #pragma unroll
            for (int mi = 0; mi < MI; ++mi) {
                MMA_B16(acc[mi][j], a[mi][0], a[mi][1], a[mi][2], a[mi][3], bv.x, bv.y); // Ah*Bh
                MMA_B16(acc[mi][j], a[mi][0], a[mi][1], a[mi][2], a[mi][3], bv.z, bv.w); // Ah*Bl
                MMA_B16(acc[mi][j], a[mi][4], a[mi][5], a[mi][6], a[mi][7], bv.x, bv.y); // Al*Bh
            }
        }
        if (kb + 1 < KB) CPWAIT();
        __syncthreads();
        p ^= 1;
    }

    #pragma unroll
    for (int mi = 0; mi < MI; ++mi)
        #pragma unroll
        for (int j = 0; j < 8; ++j)
            #pragma unroll
            for (int d = 0; d < 4; ++d) {
                int mm = m0 + wm + 16*mi + g + ((d >= 2) ? 8 : 0);
                int nn = n0 + wn + 8*j + 2*t + (d & 1);
                if (nn >= N) continue;
                float v = acc[mi][j][d];
                if (MODE == 0) {
                    if (nn < DI)           g_z[mm*DI + nn] = v;
                    else if (nn < DI + CD) g_xbc[mm*CD + nn - DI] = v;
                    else {
                        int h = nn - DI - CD;
                        float tt = v + aux1[h];
                        float sp = (tt > 20.f) ? tt : log1pf(expf(tt));
                        g_dadt[mm*H_ + h] = make_float2(sp, expf(sp * (-expf(aux2[h]))));
                    }
                } else if (MODE == 1) {
                    g_t1[mm*DM + nn] = v;
                } else if (MODE == 2) {
                    g_u[mm*DM + nn] = v + aux1[nn];
                } else {
                    int b = mm >> 11, l = mm & (L_-1);
                    outp[((b*OC) + nn)*L_ + l] = v;
                }
            }
}

// ------------------------- depthwise causal conv + SiLU -------------------
__global__ void __launch_bounds__(256)
dwconv_kernel(const float* __restrict__ w, const float* __restrict__ bias) {
    int idx = blockIdx.x*256 + threadIdx.x;
    if (idx >= B_*L_*CD) return;
    int c = idx % CD;
    int m = idx / CD;
    int l = m % L_;
    float acc = bias[c];
    #pragma unroll
    for (int k = 0; k < 4; ++k) {
        int l2 = l + k - 3;
        if (l2 >= 0) acc += g_xbc[(m - 3 + k)*CD + c] * w[c*4 + k];
    }
    float s = 1.f / (1.f + expf(-acc));
    float val = acc * s;
    if (c < DI) {
        int h = c / 3, pp = c - h*3;
        ((float*)&g_xp4[m*H_ + h])[pp] = val;
    } else {
        g_bc[m*32 + (c - DI)] = val;
    }
}

// ------------------------- scan phase A -----------------------------------
__global__ void __launch_bounds__(256) scanA_kernel() {
    int idx = blockIdx.x*256 + threadIdx.x;
    int n = idx & 15;
    int c = (idx >> 4) & 15;
    int h = (idx >> 8) & 255;
    int b = idx >> 16;
    float s0 = 0.f, s1 = 0.f, s2 = 0.f, pr = 1.f;
    int mBase = b*L_ + c*CHUNK;
    #pragma unroll 4
    for (int t = 0; t < CHUNK; ++t) {
        int m = mBase + t;
        float2 dd = g_dadt[m*H_ + h];        // (dt, dA)
        float4 xp = g_xp4[m*H_ + h];
        float Bn  = g_bc[m*32 + n];
        float w = dd.x * Bn;
        s0 = s0*dd.y + w*xp.x;
        s1 = s1*dd.y + w*xp.y;
        s2 = s2*dd.y + w*xp.z;
        pr *= dd.y;
    }
    int u = (b*H_ + h)*NC + c;
    g_cs[u*48 +      n] = s0;
    g_cs[u*48 + 16 + n] = s1;
    g_cs[u*48 + 32 + n] = s2;
    if (n == 0) g_cp[u] = pr;
}

// ------------------------- scan phase B -----------------------------------
__global__ void __launch_bounds__(256) scanB_kernel() {
    int idx = blockIdx.x*256 + threadIdx.x;
    int n = idx & 15;
    int h = (idx >> 4) & 255;
    int b = idx >> 12;
    float c0 = 0.f, c1 = 0.f, c2 = 0.f;
    for (int c = 0; c < NC; ++c) {
        int u = (b*H_ + h)*NC + c;
        g_hs[u*48 +      n] = c0;
        g_hs[u*48 + 16 + n] = c1;
        g_hs[u*48 + 32 + n] = c2;
        float pr = g_cp[u];
        c0 = c0*pr + g_cs[u*48 +      n];
        c1 = c1*pr + g_cs[u*48 + 16 + n];
        c2 = c2*pr + g_cs[u*48 + 32 + n];
    }
}

// ------------------------- scan phase C -----------------------------------
__global__ void __launch_bounds__(256) scanC_kernel(const float* __restrict__ Dp) {
    int idx = blockIdx.x*256 + threadIdx.x;
    int n = idx & 15;
    int c = (idx >> 4) & 15;
    int h = (idx >> 8) & 255;
    int b = idx >> 16;
    int u = (b*H_ + h)*NC + c;
    float s0 = g_hs[u*48 + n];
    float s1 = g_hs[u*48 + 16 + n];
    float s2 = g_hs[u*48 + 32 + n];
    float Dh = Dp[h];
    int mBase = b*L_ + c*CHUNK;
    #pragma unroll 4
    for (int t = 0; t < CHUNK; ++t) {
        int m = mBase + t;
        float2 dd = g_dadt[m*H_ + h];
        float4 xp = g_xp4[m*H_ + h];
        float Bn  = g_bc[m*32 + n];
        float Cn  = g_bc[m*32 + 16 + n];
        float w = dd.x * Bn;
        s0 = s0*dd.y + w*xp.x;
        s1 = s1*dd.y + w*xp.y;
        s2 = s2*dd.y + w*xp.z;
        float y0 = s0*Cn, y1 = s1*Cn, y2 = s2*Cn;
        #pragma unroll
        for (int off = 8; off >= 1; off >>= 1) {
            y0 += __shfl_xor_sync(0xffffffffu, y0, off);
            y1 += __shfl_xor_sync(0xffffffffu, y1, off);
            y2 += __shfl_xor_sync(0xffffffffu, y2, off);
        }
        if (n == 0) {
            float* yo = &g_y[m*DI + h*3];
            yo[0] = y0 + Dh*xp.x;
            yo[1] = y1 + Dh*xp.y;
            yo[2] = y2 + Dh*xp.z;
        }
    }
}

// ------------------------- gate + RMSNorm + pack for gemm1 ----------------
__global__ void __launch_bounds__(256)
gate_norm_kernel(const float* __restrict__ nw) {
    int m = blockIdx.x;
    int tid = threadIdx.x;
    __shared__ float red[8];
    __shared__ float ys[DI + DI/16];     // padded: index e + (e>>4)
    float yv[3];
    float acc = 0.f;
    #pragma unroll
    for (int j = 0; j < 3; ++j) {
        int e = tid*3 + j;
        float y = g_y[m*DI + e];
        float z = g_z[m*DI + e];
        float gg = y * (z / (1.f + expf(-z)));
        yv[j] = gg;
        acc += gg*gg;
    }
    #pragma unroll
    for (int off = 16; off >= 1; off >>= 1)
        acc += __shfl_xor_sync(0xffffffffu, acc, off);
    if ((tid & 31) == 0) red[tid >> 5] = acc;
    __syncthreads();
    if (tid == 0) {
        float t = 0.f;
        #pragma unroll
        for (int i = 0; i < 8; ++i) t += red[i];
        red[0] = rsqrtf(t / (float)DI + 1e-5f);
    }
    __syncthreads();
    float scale = red[0];
    #pragma unroll
    for (int j = 0; j < 3; ++j) {
        int e = tid*3 + j;
        ys[e + (e >> 4)] = yv[j] * scale * nw[e];
    }
    __syncthreads();
    if (tid < KB1) {                     // 48 k-blocks of 16, stride-17 rows
        float v[16];
        #pragma unroll
        for (int r = 0; r < 16; ++r) v[r] = ys[tid*17 + r];
        pack_block16(v, &gYp[((size_t)tid*M_ + m)*4]);
    }
}

// ------------------------- launch ----------------------------------------
extern "C" void kernel_launch(void* const* d_in, const int* in_sizes, int n_in,
                              void* d_out, int out_size) {
    const float* x           = (const float*)d_in[0];
    const float* conv_w      = (const float*)d_in[1];
    const float* conv_b      = (const float*)d_in[2];
    const float* in_proj_w   = (const float*)d_in[3];
    const float* dw_conv_w   = (const float*)d_in[4];
    const float* dw_conv_b   = (const float*)d_in[5];
    const float* dt_bias     = (const float*)d_in[6];
    const float* A_log       = (const float*)d_in[7];
    const float* Dp          = (const float*)d_in[8];
    const float* norm_w      = (const float*)d_in[9];
    const float* mamba_out_w = (const float*)d_in[10];
    const float* out_conv_w  = (const float*)d_in[11];
    float* out = (float*)d_out;

    uint4 *pW0, *pW1, *pA0, *pY, *pX, *pWc, *pT1, *pWo;
    cudaGetSymbolAddress((void**)&pW0, gW0p);
    cudaGetSymbolAddress((void**)&pW1, gW1p);
    cudaGetSymbolAddress((void**)&pA0, gA0p);
    cudaGetSymbolAddress((void**)&pY,  gYp);
    cudaGetSymbolAddress((void**)&pX,  gXp);
    cudaGetSymbolAddress((void**)&pWc, gWcp);
    cudaGetSymbolAddress((void**)&pT1, gT1p);
    cudaGetSymbolAddress((void**)&pWo, gWop);

    // weight packs (independent of data path)
    pack_W_kernel<<<(KB0*NP0 + 255)/256, 256>>>(in_proj_w,   pW0, DIP, NP0, KB0*NP0);
    pack_W_kernel<<<(KB1*DM + 255)/256, 256>>>(mamba_out_w, pW1, DM,  DM,  KB1*DM);
    pack_Wc_kernel<<<(4*KBX*DM)/256, 256>>>(conv_w);
    pack_Wo_kernel<<<(4*KBT*OC)/256, 256>>>(out_conv_w);

    // conv_in as 4-tap HMMA GEMM: M=8192, N=256, K=4x128
    pack_X_kernel<<<(KBX*M_)/256, 256>>>(x);
    hgemm_kernel<2, 128, KBX><<<dim3(DM/128, M_/128), 256>>>(
        pX, pWc, DM, DM, 4*KBX, conv_b, nullptr, nullptr);

    pack_A0_kernel<<<(KB0*M_)/256, 256>>>();

    // in_proj: M=8192, N=1824 (pad 1920), K=256
    hgemm_kernel<0, 128, 0><<<dim3(NP0/128, M_/128), 256>>>(
        pA0, pW0, NP0, DIP, KB0, dt_bias, A_log, nullptr);

    dwconv_kernel<<<(B_*L_*CD + 255)/256, 256>>>(dw_conv_w, dw_conv_b);

    scanA_kernel<<<(B_*H_*NC*NS)/256, 256>>>();
    scanB_kernel<<<(B_*H_*NS)/256, 256>>>();
    scanC_kernel<<<(B_*H_*NC*NS)/256, 256>>>(Dp);

    gate_norm_kernel<<<M_, 256>>>(norm_w);

    // out_proj: M=8192, N=256, K=768
    hgemm_kernel<1, 128, 0><<<dim3(DM/128, M_/128), 256>>>(
        pY, pW1, DM, DM, KB1, nullptr, nullptr, nullptr);

    // conv_out as 4-tap HMMA GEMM: M=8192 (TM=64), N=128, K=4x256
    pack_T1_kernel<<<(KBT*M_)/256, 256>>>();
    hgemm_kernel<3, 64, KBT><<<dim3(OC/128, M_/64), 256>>>(
        pT1, pWo, OC, OC, 4*KBT, nullptr, nullptr, out);
}

// round 10
// speedup vs baseline: 2.0188x; 1.1186x over previous
#include <cuda_runtime.h>
#include <cuda_bf16.h>
#include <math.h>

// Problem constants
#define B_    4
#define L_    2048
#define DM    256     // d_model
#define DI    768     // d_inner
#define H_    256     // nheads
#define NS    16      // d_state
#define CD    800     // conv_dim = DI + 2*NS
#define DIP   1824    // d_in_proj
#define INC   128     // input channels
#define OC    128     // output channels
#define NC    16      // scan chunks
#define CHUNK 128     // L per chunk
#define M_    (B_*L_) // 8192 rows
#define NP0   1920    // padded N for gemm0 (15 * 128)
#define KB0   16      // 256/16 (in_proj K blocks)
#define KB1   48      // 768/16 (out_proj K blocks)
#define KBX   8       // 128/16 (x channels K blocks, per tap)
#define KBT   16      // 256/16 (t1 channels K blocks, per tap)

// ------------------------- scratch (device globals) -----------------------
__device__ float  g_z   [M_*DI];        // gate branch
__device__ float  g_xbc [M_*CD];        // pre-dwconv
__device__ float  g_y   [M_*DI];        // scan output
__device__ float2 g_dadt[M_*H_];        // (softplus dt, exp(dt*A))
__device__ float4 g_xp4 [M_*H_];        // x padded: [m][h] -> (x0,x1,x2,unused)
__device__ float  g_bc  [M_*32];        // [m][0:16]=B, [16:32]=C
__device__ float  g_cs  [B_*H_*NC*3*NS];
__device__ float  g_hs  [B_*H_*NC*3*NS];
__device__ float  g_cp  [B_*H_*NC];
// bf16-split packed operands: per (kblk,row): 4 x uint4 of
// [hi pair(2t,2t+1) | hi pair(2t+8,2t+9) | lo pair | lo pair]
__device__ uint4  gA0p[KB0*M_*4];       // in_proj A (written by conv_in epilogue)
__device__ uint4  gW0p[KB0*NP0*4];      // in_proj W packed
__device__ uint4  gYp [KB1*M_*4];       // out_proj A (from gate_norm)
__device__ uint4  gW1p[KB1*DM*4];       // out_proj W packed
__device__ uint4  gXp [KBX*M_*4];       // x transposed+packed [kb][m]
__device__ uint4  gWcp[4*KBX*DM*4];     // conv_in W packed, kb_eff = tap*8+kbx
__device__ uint4  gT1p[KBT*M_*4];       // out_proj result packed (epilogue)
__device__ uint4  gWop[4*KBT*OC*4];     // conv_out W packed
__device__ uint4  g_zero4[4];           // static zeros for invalid conv rows

// ------------------------- bf16 split helpers -----------------------------
__device__ __forceinline__ void split2(float a, float b, unsigned &hw, unsigned &lw) {
    __nv_bfloat16 ah = __float2bfloat16(a);
    __nv_bfloat16 bh = __float2bfloat16(b);
    float ar = a - __bfloat162float(ah);
    float br = b - __bfloat162float(bh);
    __nv_bfloat16 al = __float2bfloat16(ar);
    __nv_bfloat16 bl = __float2bfloat16(br);
    hw = ((unsigned)__bfloat16_as_ushort(bh) << 16) | (unsigned)__bfloat16_as_ushort(ah);
    lw = ((unsigned)__bfloat16_as_ushort(bl) << 16) | (unsigned)__bfloat16_as_ushort(al);
}
__device__ __forceinline__ void pack_block16(const float* v, uint4* dst) {
    #pragma unroll
    for (int t = 0; t < 4; ++t) {
        unsigned h0, l0, h1, l1;
        split2(v[2*t],     v[2*t + 1], h0, l0);
        split2(v[2*t + 8], v[2*t + 9], h1, l1);
        dst[t] = make_uint4(h0, h1, l0, l1);
    }
}

// ------------------------- pack kernels ------------------------------------
__global__ void __launch_bounds__(256) pack_X_kernel(const float* __restrict__ x) {
    int idx = blockIdx.x*256 + threadIdx.x;       // kb*M + m, kb 0..7
    int kb = idx >> 13, m = idx & (M_ - 1);
    int b = m >> 11, l = m & 2047;
    float v[16];
    #pragma unroll
    for (int r = 0; r < 16; ++r) v[r] = x[(b*INC + kb*16 + r)*L_ + l];
    pack_block16(v, &gXp[(size_t)idx*4]);
}
// all four weight packs in one launch
#define SEG0 (KB0*NP0)          // in_proj W
#define SEG1 (SEG0 + KB1*DM)    // out_proj W
#define SEG2 (SEG1 + 4*KBX*DM)  // conv_in W
#define SEG3 (SEG2 + 4*KBT*OC)  // conv_out W
__global__ void __launch_bounds__(256)
pack_weights_kernel(const float* __restrict__ Wip, const float* __restrict__ Wmo,
                    const float* __restrict__ Wc,  const float* __restrict__ Wo) {
    int idx = blockIdx.x*256 + threadIdx.x;
    float v[16];
    if (idx < SEG0) {                              // in_proj [256,1824] -> [kb][n pad 1920]
        int kb = idx / NP0, n = idx % NP0;
        #pragma unroll
        for (int r = 0; r < 16; ++r)
            v[r] = (n < DIP) ? Wip[(kb*16 + r)*DIP + n] : 0.f;
        pack_block16(v, &gW0p[(size_t)idx*4]);
    } else if (idx < SEG1) {                       // mamba_out [768,256]
        int i = idx - SEG0;
        int kb = i / DM, n = i % DM;
        #pragma unroll
        for (int r = 0; r < 16; ++r) v[r] = Wmo[(kb*16 + r)*DM + n];
        pack_block16(v, &gW1p[(size_t)i*4]);
    } else if (idx < SEG2) {                       // conv_in w [256][128][4]
        int i = idx - SEG1;
        int kbe = i >> 8, co = i & 255;
        int tap = kbe >> 3, kbx = kbe & 7;
        #pragma unroll
        for (int r = 0; r < 16; ++r) v[r] = Wc[(co*INC + kbx*16 + r)*4 + tap];
        pack_block16(v, &gWcp[(size_t)i*4]);
    } else if (idx < SEG3) {                       // conv_out w [128][256][4]
        int i = idx - SEG2;
        int kbe = i >> 7, o = i & 127;
        int tap = kbe >> 4, kbx = kbe & 15;
        #pragma unroll
        for (int r = 0; r < 16; ++r) v[r] = Wo[(o*DM + kbx*16 + r)*4 + tap];
        pack_block16(v, &gWop[(size_t)i*4]);
    }
}

// ------------------------- HMMA GEMM (bf16 3-term split, fp32 acc) --------
#define MMA_B16(d, a0,a1,a2,a3, b0,b1) \
    asm volatile("mma.sync.aligned.m16n8k16.row.col.f32.bf16.bf16.f32 " \
        "{%0,%1,%2,%3}, {%4,%5,%6,%7}, {%8,%9}, {%0,%1,%2,%3};" \
        : "+f"(d[0]), "+f"(d[1]), "+f"(d[2]), "+f"(d[3]) \
        : "r"(a0), "r"(a1), "r"(a2), "r"(a3), "r"(b0), "r"(b1))
#define CPA16(s, g) asm volatile("cp.async.cg.shared.global [%0], [%1], 16;" :: "r"(s), "l"(g))
#define CPCOMMIT()  asm volatile("cp.async.commit_group;")
#define CPWAIT1()   asm volatile("cp.async.wait_group 1;")

// TM x 128 CTA tile, 8 warps, warp tile (TM/4)x64, K-step 16, 3-stage pipeline.
// CONV_KBI != 0: K blocks = 4 taps x CONV_KBI; A rows shifted by (tap-1) with
// zero-fill outside the batch's [0,L) range.
// MODE 0: in_proj epilogue (z / xbc / softplus-dt + dA)
// MODE 1: out_proj -> packed gT1p directly (fragment layout == pack layout)
// MODE 2: conv_in  -> + bias, packed gA0p directly
// MODE 3: conv_out -> transpose store to out[b][o][l]
template<int MODE, int TM, int CONV_KBI>
__global__ void __launch_bounds__(256)
hgemm_kernel(const uint4* __restrict__ Ap, const uint4* __restrict__ Bp,
             int NPad, int N, int KB,
             const float* __restrict__ aux1, const float* __restrict__ aux2,
             float* __restrict__ outp) {
    constexpr int ATILE = TM * 4;                 // uint4 per A tile
    constexpr int MI = TM / 64;
    __shared__ uint4 sb[3][ATILE + 512];          // 3-stage ring
    int tid  = threadIdx.x;
    int m0   = blockIdx.y * TM, n0 = blockIdx.x * 128;
    int lane = tid & 31, warp = tid >> 5;
    int g = lane >> 2, t = lane & 3;
    int wm = (warp >> 1) * (TM/4), wn = (warp & 1) * 64;

    float acc[MI][8][4];
    #pragma unroll
    for (int mi = 0; mi < MI; ++mi)
        #pragma unroll
        for (int j = 0; j < 8; ++j)
            #pragma unroll
            for (int d = 0; d < 4; ++d) acc[mi][j][d] = 0.f;

    auto copy_tile = [&](int kbe, int buf) {
        int kbx = kbe, shift = 0;
        if (CONV_KBI) { kbx = kbe & (CONV_KBI-1); shift = (kbe / CONV_KBI) - 1; }
        // ---- A tile ----
        if (TM == 128) {
            int crow = tid >> 1, coff = (tid & 1) * 2;
            const uint4* asrc = Ap + ((size_t)kbx*M_ + m0 + crow + shift)*4 + coff;
            if (CONV_KBI) {
                int ld = ((m0 + crow) & (L_-1)) + shift;
                if ((unsigned)ld >= (unsigned)L_) asrc = g_zero4;
            }
            unsigned sa = (unsigned)__cvta_generic_to_shared(&sb[buf][crow*4 + coff]);
            CPA16(sa,      asrc);
            CPA16(sa + 16, asrc + 1);
        } else {
            int arow = tid >> 2, aslot = tid & 3;
            const uint4* asrc = Ap + ((size_t)kbx*M_ + m0 + arow + shift)*4 + aslot;
            if (CONV_KBI) {
                int ld = ((m0 + arow) & (L_-1)) + shift;
                if ((unsigned)ld >= (unsigned)L_) asrc = g_zero4;
            }
            unsigned sa = (unsigned)__cvta_generic_to_shared(&sb[buf][arow*4 + aslot]);
            CPA16(sa, asrc);
        }
        // ---- B tile (always 128 rows) ----
        {
            int brow = tid >> 1, bcoff = (tid & 1) * 2;
            const uint4* bsrc = Bp + ((size_t)kbe*NPad + n0 + brow)*4 + bcoff;
            unsigned sB = (unsigned)__cvta_generic_to_shared(&sb[buf][ATILE + brow*4 + bcoff]);
            CPA16(sB,      bsrc);
            CPA16(sB + 16, bsrc + 1);
        }
    };

    // 3-stage prologue
    copy_tile(0, 0); CPCOMMIT();
    if (KB > 1) copy_tile(1, 1);
    CPCOMMIT();

    for (int kb = 0; kb < KB; ++kb) {
        CPWAIT1();              // group kb complete (kb+1 may be in flight)
        __syncthreads();        // also protects buffer (kb+2)%3 from overwrite
        if (kb + 2 < KB) copy_tile(kb + 2, (kb + 2) % 3);
        CPCOMMIT();             // always commit to keep group counts aligned
        const uint4* As = sb[kb % 3];
        const uint4* Bs = sb[kb % 3] + ATILE;
        unsigned a[MI][8];
        #pragma unroll
        for (int mi = 0; mi < MI; ++mi) {
            uint4 v0 = As[(wm + 16*mi + g)*4 + t];
            uint4 v1 = As[(wm + 16*mi + g + 8)*4 + t];
            a[mi][0] = v0.x; a[mi][2] = v0.y; a[mi][4] = v0.z; a[mi][6] = v0.w;
            a[mi][1] = v1.x; a[mi][3] = v1.y; a[mi][5] = v1.z; a[mi][7] = v1.w;
        }
        #pragma unroll
        for (int j = 0; j < 8; ++j) {
            uint4 bv = Bs[(wn + 8*j + g)*4 + t];
            #pragma unroll
            for (int mi = 0; mi < MI; ++mi) {
                MMA_B16(acc[mi][j], a[mi][0], a[mi][1], a[mi][2], a[mi][3], bv.x, bv.y); // Ah*Bh
                MMA_B16(acc[mi][j], a[mi][0], a[mi][1], a[mi][2], a[mi][3], bv.z, bv.w); // Ah*Bl
                MMA_B16(acc[mi][j], a[mi][4], a[mi][5], a[mi][6], a[mi][7], bv.x, bv.y); // Al*Bh
            }
        }
    }

    if (MODE == 1 || MODE == 2) {
        // Packed epilogue: lane (g,t) fragment == pack slot t of the 16-block.
        // Row r0 holds d=0,1; row r0+8 holds d=2,3. N % 128 == 0 here.
        uint4* dstBase = (MODE == 1) ? gT1p : gA0p;
        #pragma unroll
        for (int mi = 0; mi < MI; ++mi) {
            int r0 = m0 + wm + 16*mi + g;
            #pragma unroll
            for (int k = 0; k < 4; ++k) {
                int kb = (n0 + wn)/16 + k;
                float b0 = 0.f, b1 = 0.f, b2 = 0.f, b3 = 0.f;
                if (MODE == 2) {
                    int colBase = n0 + wn + 16*k;
                    b0 = aux1[colBase + 2*t];
                    b1 = aux1[colBase + 2*t + 1];
                    b2 = aux1[colBase + 2*t + 8];
                    b3 = aux1[colBase + 2*t + 9];
                }
                unsigned h0, l0, h1, l1;
                split2(acc[mi][2*k][0] + b0, acc[mi][2*k][1] + b1, h0, l0);
                split2(acc[mi][2*k+1][0] + b2, acc[mi][2*k+1][1] + b3, h1, l1);
                dstBase[((size_t)kb*M_ + r0)*4 + t] = make_uint4(h0, h1, l0, l1);
                split2(acc[mi][2*k][2] + b0, acc[mi][2*k][3] + b1, h0, l0);
                split2(acc[mi][2*k+1][2] + b2, acc[mi][2*k+1][3] + b3, h1, l1);
                dstBase[((size_t)kb*M_ + r0 + 8)*4 + t] = make_uint4(h0, h1, l0, l1);
            }
        }
        return;
    }

    #pragma unroll
    for (int mi = 0; mi < MI; ++mi)
        #pragma unroll
        for (int j = 0; j < 8; ++j)
            #pragma unroll
            for (int d = 0; d < 4; ++d) {
                int mm = m0 + wm + 16*mi + g + ((d >= 2) ? 8 : 0);
                int nn = n0 + wn + 8*j + 2*t + (d & 1);
                if (nn >= N) continue;
                float v = acc[mi][j][d];
                if (MODE == 0) {
                    if (nn < DI)           g_z[mm*DI + nn] = v;
                    else if (nn < DI + CD) g_xbc[mm*CD + nn - DI] = v;
                    else {
                        int h = nn - DI - CD;
                        float tt = v + aux1[h];
                        float sp = (tt > 20.f) ? tt : log1pf(expf(tt));
                        g_dadt[mm*H_ + h] = make_float2(sp, expf(sp * (-expf(aux2[h]))));
                    }
                } else {
                    int b = mm >> 11, l = mm & (L_-1);
                    outp[((b*OC) + nn)*L_ + l] = v;
                }
            }
}

// ------------------------- depthwise causal conv + SiLU -------------------
__global__ void __launch_bounds__(256)
dwconv_kernel(const float* __restrict__ w, const float* __restrict__ bias) {
    int idx = blockIdx.x*256 + threadIdx.x;
    if (idx >= B_*L_*CD) return;
    int c = idx % CD;
    int m = idx / CD;
    int l = m % L_;
    float acc = bias[c];
    #pragma unroll
    for (int k = 0; k < 4; ++k) {
        int l2 = l + k - 3;
        if (l2 >= 0) acc += g_xbc[(m - 3 + k)*CD + c] * w[c*4 + k];
    }
    float s = 1.f / (1.f + expf(-acc));
    float val = acc * s;
    if (c < DI) {
        int h = c / 3, pp = c - h*3;
        ((float*)&g_xp4[m*H_ + h])[pp] = val;
    } else {
        g_bc[m*32 + (c - DI)] = val;
    }
}

// ------------------------- scan phase A -----------------------------------
__global__ void __launch_bounds__(256) scanA_kernel() {
    int idx = blockIdx.x*256 + threadIdx.x;
    int n = idx & 15;
    int c = (idx >> 4) & 15;
    int h = (idx >> 8) & 255;
    int b = idx >> 16;
    float s0 = 0.f, s1 = 0.f, s2 = 0.f, pr = 1.f;
    int mBase = b*L_ + c*CHUNK;
    #pragma unroll 4
    for (int t = 0; t < CHUNK; ++t) {
        int m = mBase + t;
        float2 dd = g_dadt[m*H_ + h];        // (dt, dA)
        float4 xp = g_xp4[m*H_ + h];
        float Bn  = g_bc[m*32 + n];
        float w = dd.x * Bn;
        s0 = s0*dd.y + w*xp.x;
        s1 = s1*dd.y + w*xp.y;
        s2 = s2*dd.y + w*xp.z;
        pr *= dd.y;
    }
    int u = (b*H_ + h)*NC + c;
    g_cs[u*48 +      n] = s0;
    g_cs[u*48 + 16 + n] = s1;
    g_cs[u*48 + 32 + n] = s2;
    if (n == 0) g_cp[u] = pr;
}

// ------------------------- scan phase B -----------------------------------
__global__ void __launch_bounds__(256) scanB_kernel() {
    int idx = blockIdx.x*256 + threadIdx.x;
    int n = idx & 15;
    int h = (idx >> 4) & 255;
    int b = idx >> 12;
    float c0 = 0.f, c1 = 0.f, c2 = 0.f;
    for (int c = 0; c < NC; ++c) {
        int u = (b*H_ + h)*NC + c;
        g_hs[u*48 +      n] = c0;
        g_hs[u*48 + 16 + n] = c1;
        g_hs[u*48 + 32 + n] = c2;
        float pr = g_cp[u];
        c0 = c0*pr + g_cs[u*48 +      n];
        c1 = c1*pr + g_cs[u*48 + 16 + n];
        c2 = c2*pr + g_cs[u*48 + 32 + n];
    }
}

// ------------------------- scan phase C -----------------------------------
__global__ void __launch_bounds__(256) scanC_kernel(const float* __restrict__ Dp) {
    int idx = blockIdx.x*256 + threadIdx.x;
    int n = idx & 15;
    int c = (idx >> 4) & 15;
    int h = (idx >> 8) & 255;
    int b = idx >> 16;
    int u = (b*H_ + h)*NC + c;
    float s0 = g_hs[u*48 + n];
    float s1 = g_hs[u*48 + 16 + n];
    float s2 = g_hs[u*48 + 32 + n];
    float Dh = Dp[h];
    int mBase = b*L_ + c*CHUNK;
    #pragma unroll 4
    for (int t = 0; t < CHUNK; ++t) {
        int m = mBase + t;
        float2 dd = g_dadt[m*H_ + h];
        float4 xp = g_xp4[m*H_ + h];
        float Bn  = g_bc[m*32 + n];
        float Cn  = g_bc[m*32 + 16 + n];
        float w = dd.x * Bn;
        s0 = s0*dd.y + w*xp.x;
        s1 = s1*dd.y + w*xp.y;
        s2 = s2*dd.y + w*xp.z;
        float y0 = s0*Cn, y1 = s1*Cn, y2 = s2*Cn;
        #pragma unroll
        for (int off = 8; off >= 1; off >>= 1) {
            y0 += __shfl_xor_sync(0xffffffffu, y0, off);
            y1 += __shfl_xor_sync(0xffffffffu, y1, off);
            y2 += __shfl_xor_sync(0xffffffffu, y2, off);
        }
        if (n == 0) {
            float* yo = &g_y[m*DI + h*3];
            yo[0] = y0 + Dh*xp.x;
            yo[1] = y1 + Dh*xp.y;
            yo[2] = y2 + Dh*xp.z;
        }
    }
}

// ------------------------- gate + RMSNorm + pack for gemm1 ----------------
__global__ void __launch_bounds__(256)
gate_norm_kernel(const float* __restrict__ nw) {
    int m = blockIdx.x;
    int tid = threadIdx.x;
    __shared__ float red[8];
    __shared__ float ys[DI + DI/16];     // padded: index e + (e>>4)
    float yv[3];
    float acc = 0.f;
    #pragma unroll
    for (int j = 0; j < 3; ++j) {
        int e = tid*3 + j;
        float y = g_y[m*DI + e];
        float z = g_z[m*DI + e];
        float gg = y * (z / (1.f + expf(-z)));
        yv[j] = gg;
        acc += gg*gg;
    }
    #pragma unroll
    for (int off = 16; off >= 1; off >>= 1)
        acc += __shfl_xor_sync(0xffffffffu, acc, off);
    if ((tid & 31) == 0) red[tid >> 5] = acc;
    __syncthreads();
    if (tid == 0) {
        float t = 0.f;
        #pragma unroll
        for (int i = 0; i < 8; ++i) t += red[i];
        red[0] = rsqrtf(t / (float)DI + 1e-5f);
    }
    __syncthreads();
    float scale = red[0];
    #pragma unroll
    for (int j = 0; j < 3; ++j) {
        int e = tid*3 + j;
        ys[e + (e >> 4)] = yv[j] * scale * nw[e];
    }
    __syncthreads();
    if (tid < KB1) {                     // 48 k-blocks of 16, stride-17 rows
        float v[16];
        #pragma unroll
        for (int r = 0; r < 16; ++r) v[r] = ys[tid*17 + r];
        pack_block16(v, &gYp[((size_t)tid*M_ + m)*4]);
    }
}

// ------------------------- launch ----------------------------------------
extern "C" void kernel_launch(void* const* d_in, const int* in_sizes, int n_in,
                              void* d_out, int out_size) {
    const float* x           = (const float*)d_in[0];
    const float* conv_w      = (const float*)d_in[1];
    const float* conv_b      = (const float*)d_in[2];
    const float* in_proj_w   = (const float*)d_in[3];
    const float* dw_conv_w   = (const float*)d_in[4];
    const float* dw_conv_b   = (const float*)d_in[5];
    const float* dt_bias     = (const float*)d_in[6];
    const float* A_log       = (const float*)d_in[7];
    const float* Dp          = (const float*)d_in[8];
    const float* norm_w      = (const float*)d_in[9];
    const float* mamba_out_w = (const float*)d_in[10];
    const float* out_conv_w  = (const float*)d_in[11];
    float* out = (float*)d_out;

    uint4 *pW0, *pW1, *pA0, *pY, *pX, *pWc, *pT1, *pWo;
    cudaGetSymbolAddress((void**)&pW0, gW0p);
    cudaGetSymbolAddress((void**)&pW1, gW1p);
    cudaGetSymbolAddress((void**)&pA0, gA0p);
    cudaGetSymbolAddress((void**)&pY,  gYp);
    cudaGetSymbolAddress((void**)&pX,  gXp);
    cudaGetSymbolAddress((void**)&pWc, gWcp);
    cudaGetSymbolAddress((void**)&pT1, gT1p);
    cudaGetSymbolAddress((void**)&pWo, gWop);

    // all weight packs in one launch
    pack_weights_kernel<<<(SEG3 + 255)/256, 256>>>(in_proj_w, mamba_out_w,
                                                   conv_w, out_conv_w);

    // conv_in as 4-tap HMMA GEMM: M=8192, N=256, K=4x128 -> packed gA0p
    pack_X_kernel<<<(KBX*M_)/256, 256>>>(x);
    hgemm_kernel<2, 128, KBX><<<dim3(DM/128, M_/128), 256>>>(
        pX, pWc, DM, DM, 4*KBX, conv_b, nullptr, nullptr);

    // in_proj: M=8192, N=1824 (pad 1920), K=256
    hgemm_kernel<0, 128, 0><<<dim3(NP0/128, M_/128), 256>>>(
        pA0, pW0, NP0, DIP, KB0, dt_bias, A_log, nullptr);

    dwconv_kernel<<<(B_*L_*CD + 255)/256, 256>>>(dw_conv_w, dw_conv_b);

    scanA_kernel<<<(B_*H_*NC*NS)/256, 256>>>();
    scanB_kernel<<<(B_*H_*NS)/256, 256>>>();
    scanC_kernel<<<(B_*H_*NC*NS)/256, 256>>>(Dp);

    gate_norm_kernel<<<M_, 256>>>(norm_w);

    // out_proj: M=8192, N=256, K=768 -> packed gT1p
    hgemm_kernel<1, 128, 0><<<dim3(DM/128, M_/128), 256>>>(
        pY, pW1, DM, DM, KB1, nullptr, nullptr, nullptr);

    // conv_out as 4-tap HMMA GEMM: M=8192 (TM=64), N=128, K=4x256
    hgemm_kernel<3, 64, KBT><<<dim3(OC/128, M_/64), 256>>>(
        pT1, pWo, OC, OC, 4*KBT, nullptr, nullptr, out);
}

// round 15
// speedup vs baseline: 2.0640x; 1.0224x over previous
#include <cuda_runtime.h>
#include <cuda_bf16.h>
#include <math.h>

// Problem constants
#define B_    4
#define L_    2048
#define DM    256     // d_model
#define DI    768     // d_inner
#define H_    256     // nheads
#define NS    16      // d_state
#define CD    800     // conv_dim = DI + 2*NS
#define DIP   1824    // d_in_proj
#define INC   128     // input channels
#define OC    128     // output channels
#define NC    16      // scan chunks
#define CHUNK 128     // L per chunk
#define M_    (B_*L_) // 8192 rows
#define NP0   1920    // padded N for gemm0 (15 * 128)
#define KB0   16      // 256/16 (in_proj K blocks)
#define KB1   48      // 768/16 (out_proj K blocks)
#define KBX   8       // 128/16 (x channels K blocks, per tap)
#define KBT   16      // 256/16 (t1 channels K blocks, per tap)

// ------------------------- scratch (device globals) -----------------------
__device__ float  g_z   [M_*DI];
__device__ float  g_xbc [M_*CD];
__device__ float  g_y   [M_*DI];
__device__ float2 g_dadt[M_*H_];
__device__ float4 g_xp4 [M_*H_];
__device__ float  g_bc  [M_*32];
__device__ float  g_cs  [B_*H_*NC*3*NS];
__device__ float  g_hs  [B_*H_*NC*3*NS];
__device__ float  g_cp  [B_*H_*NC];
// bf16-split packed operands: per (kblk,row): 4 x uint4 of
// [hi pair(2t,2t+1) | hi pair(2t+8,2t+9) | lo pair | lo pair]
__device__ uint4  gA0p[KB0*M_*4];
__device__ uint4  gW0p[KB0*NP0*4];
__device__ uint4  gYp [KB1*M_*4];
__device__ uint4  gW1p[KB1*DM*4];
__device__ uint4  gXp [KBX*M_*4];
__device__ uint4  gWcp[4*KBX*DM*4];
__device__ uint4  gT1p[KBT*M_*4];
__device__ uint4  gWop[4*KBT*OC*4];
__device__ uint4  g_zero4[4];

// ------------------------- bf16 split helpers -----------------------------
__device__ __forceinline__ void split2(float a, float b, unsigned &hw, unsigned &lw) {
    __nv_bfloat16 ah = __float2bfloat16(a);
    __nv_bfloat16 bh = __float2bfloat16(b);
    float ar = a - __bfloat162float(ah);
    float br = b - __bfloat162float(bh);
    __nv_bfloat16 al = __float2bfloat16(ar);
    __nv_bfloat16 bl = __float2bfloat16(br);
    hw = ((unsigned)__bfloat16_as_ushort(bh) << 16) | (unsigned)__bfloat16_as_ushort(ah);
    lw = ((unsigned)__bfloat16_as_ushort(bl) << 16) | (unsigned)__bfloat16_as_ushort(al);
}
__device__ __forceinline__ void pack_block16(const float* v, uint4* dst) {
    #pragma unroll
    for (int t = 0; t < 4; ++t) {
        unsigned h0, l0, h1, l1;
        split2(v[2*t],     v[2*t + 1], h0, l0);
        split2(v[2*t + 8], v[2*t + 9], h1, l1);
        dst[t] = make_uint4(h0, h1, l0, l1);
    }
}

// ------------------------- pack kernels ------------------------------------
__global__ void __launch_bounds__(256) pack_X_kernel(const float* __restrict__ x) {
    int idx = blockIdx.x*256 + threadIdx.x;       // kb*M + m, kb 0..7
    int kb = idx >> 13, m = idx & (M_ - 1);
    int b = m >> 11, l = m & 2047;
    float v[16];
    #pragma unroll
    for (int r = 0; r < 16; ++r) v[r] = x[(b*INC + kb*16 + r)*L_ + l];
    pack_block16(v, &gXp[(size_t)idx*4]);
}
#define SEG0 (KB0*NP0)
#define SEG1 (SEG0 + KB1*DM)
#define SEG2 (SEG1 + 4*KBX*DM)
#define SEG3 (SEG2 + 4*KBT*OC)
__global__ void __launch_bounds__(256)
pack_weights_kernel(const float* __restrict__ Wip, const float* __restrict__ Wmo,
                    const float* __restrict__ Wc,  const float* __restrict__ Wo) {
    int idx = blockIdx.x*256 + threadIdx.x;
    float v[16];
    if (idx < SEG0) {
        int kb = idx / NP0, n = idx % NP0;
        #pragma unroll
        for (int r = 0; r < 16; ++r)
            v[r] = (n < DIP) ? Wip[(kb*16 + r)*DIP + n] : 0.f;
        pack_block16(v, &gW0p[(size_t)idx*4]);
    } else if (idx < SEG1) {
        int i = idx - SEG0;
        int kb = i / DM, n = i % DM;
        #pragma unroll
        for (int r = 0; r < 16; ++r) v[r] = Wmo[(kb*16 + r)*DM + n];
        pack_block16(v, &gW1p[(size_t)i*4]);
    } else if (idx < SEG2) {
        int i = idx - SEG1;
        int kbe = i >> 8, co = i & 255;
        int tap = kbe >> 3, kbx = kbe & 7;
        #pragma unroll
        for (int r = 0; r < 16; ++r) v[r] = Wc[(co*INC + kbx*16 + r)*4 + tap];
        pack_block16(v, &gWcp[(size_t)i*4]);
    } else if (idx < SEG3) {
        int i = idx - SEG2;
        int kbe = i >> 7, o = i & 127;
        int tap = kbe >> 4, kbx = kbe & 15;
        #pragma unroll
        for (int r = 0; r < 16; ++r) v[r] = Wo[(o*DM + kbx*16 + r)*4 + tap];
        pack_block16(v, &gWop[(size_t)i*4]);
    }
}

// ------------------------- HMMA GEMM (bf16 3-term split, fp32 acc) --------
#define MMA_B16(d, a0,a1,a2,a3, b0,b1) \
    asm volatile("mma.sync.aligned.m16n8k16.row.col.f32.bf16.bf16.f32 " \
        "{%0,%1,%2,%3}, {%4,%5,%6,%7}, {%8,%9}, {%0,%1,%2,%3};" \
        : "+f"(d[0]), "+f"(d[1]), "+f"(d[2]), "+f"(d[3]) \
        : "r"(a0), "r"(a1), "r"(a2), "r"(a3), "r"(b0), "r"(b1))
#define CPA16(s, g) asm volatile("cp.async.cg.shared.global [%0], [%1], 16;" :: "r"(s), "l"(g))
#define CPCOMMIT()  asm volatile("cp.async.commit_group;")
#define CPWAIT1()   asm volatile("cp.async.wait_group 1;")

// TM x 128 CTA tile, 8 warps, warp tile (TM/4)x64. K-step 32 (two 16-K
// sub-blocks per pipeline stage), 3-stage ring in dynamic smem.
// KBP = number of 32-K pairs. CONV_KBI: per-tap 16-K block count (even, so
// taps never straddle a pair); A rows shifted by (tap-1), zero-filled
// outside the batch's [0,L) range.
// MODE 0: in_proj epilogue | 1: ->gT1p packed | 2: conv_in +bias ->gA0p | 3: conv_out ->out
template<int MODE, int TM, int CONV_KBI>
__global__ void __launch_bounds__(256)
hgemm_kernel(const uint4* __restrict__ Ap, const uint4* __restrict__ Bp,
             int NPad, int N, int KBP,
             const float* __restrict__ aux1, const float* __restrict__ aux2,
             float* __restrict__ outp) {
    constexpr int AT = TM * 4;                // uint4 per 16-K A tile
    constexpr int STG = 2*AT + 1024;          // uint4 per stage (A0 A1 B0 B1)
    constexpr int MI = TM / 64;
    extern __shared__ uint4 sb[];
    int tid  = threadIdx.x;
    int m0   = blockIdx.y * TM, n0 = blockIdx.x * 128;
    int lane = tid & 31, warp = tid >> 5;
    int g = lane >> 2, t = lane & 3;
    int wm = (warp >> 1) * (TM/4), wn = (warp & 1) * 64;

    float acc[MI][8][4];
    #pragma unroll
    for (int mi = 0; mi < MI; ++mi)
        #pragma unroll
        for (int j = 0; j < 8; ++j)
            #pragma unroll
            for (int d = 0; d < 4; ++d) acc[mi][j][d] = 0.f;

    auto copy_pair = [&](int qp, int buf) {
        uint4* st = sb + buf*STG;
        #pragma unroll
        for (int s = 0; s < 2; ++s) {
            int kbe = 2*qp + s;
            int kbx = kbe, shift = 0;
            if (CONV_KBI) { kbx = kbe & (CONV_KBI-1); shift = (kbe / CONV_KBI) - 1; }
            // ---- A sub-tile ----
            if (TM == 128) {
                int crow = tid >> 1, coff = (tid & 1) * 2;
                const uint4* asrc = Ap + ((size_t)kbx*M_ + m0 + crow + shift)*4 + coff;
                if (CONV_KBI) {
                    int ld = ((m0 + crow) & (L_-1)) + shift;
                    if ((unsigned)ld >= (unsigned)L_) asrc = g_zero4;
                }
                unsigned sa = (unsigned)__cvta_generic_to_shared(&st[s*AT + crow*4 + coff]);
                CPA16(sa,      asrc);
                CPA16(sa + 16, asrc + 1);
            } else {
                int arow = tid >> 2, aslot = tid & 3;
                const uint4* asrc = Ap + ((size_t)kbx*M_ + m0 + arow + shift)*4 + aslot;
                if (CONV_KBI) {
                    int ld = ((m0 + arow) & (L_-1)) + shift;
                    if ((unsigned)ld >= (unsigned)L_) asrc = g_zero4;
                }
                unsigned sa = (unsigned)__cvta_generic_to_shared(&st[s*AT + arow*4 + aslot]);
                CPA16(sa, asrc);
            }
            // ---- B sub-tile ----
            {
                int brow = tid >> 1, bcoff = (tid & 1) * 2;
                const uint4* bsrc = Bp + ((size_t)kbe*NPad + n0 + brow)*4 + bcoff;
                unsigned sB = (unsigned)__cvta_generic_to_shared(&st[2*AT + s*512 + brow*4 + bcoff]);
                CPA16(sB,      bsrc);
                CPA16(sB + 16, bsrc + 1);
            }
        }
    };

    copy_pair(0, 0); CPCOMMIT();
    if (KBP > 1) copy_pair(1, 1);
    CPCOMMIT();

    for (int qp = 0; qp < KBP; ++qp) {
        CPWAIT1();
        __syncthreads();
        if (qp + 2 < KBP) copy_pair(qp + 2, (qp + 2) % 3);
        CPCOMMIT();
        const uint4* st = sb + (qp % 3)*STG;
        #pragma unroll
        for (int s = 0; s < 2; ++s) {
            const uint4* As = st + s*AT;
            const uint4* Bs = st + 2*AT + s*512;
            unsigned a[MI][8];
            #pragma unroll
            for (int mi = 0; mi < MI; ++mi) {
                uint4 v0 = As[(wm + 16*mi + g)*4 + t];
                uint4 v1 = As[(wm + 16*mi + g + 8)*4 + t];
                a[mi][0] = v0.x; a[mi][2] = v0.y; a[mi][4] = v0.z; a[mi][6] = v0.w;
                a[mi][1] = v1.x; a[mi][3] = v1.y; a[mi][5] = v1.z; a[mi][7] = v1.w;
            }
            #pragma unroll
            for (int j = 0; j < 8; ++j) {
                uint4 bv = Bs[(wn + 8*j + g)*4 + t];
                #pragma unroll
                for (int mi = 0; mi < MI; ++mi) {
                    MMA_B16(acc[mi][j], a[mi][0], a[mi][1], a[mi][2], a[mi][3], bv.x, bv.y);
                    MMA_B16(acc[mi][j], a[mi][0], a[mi][1], a[mi][2], a[mi][3], bv.z, bv.w);
                    MMA_B16(acc[mi][j], a[mi][4], a[mi][5], a[mi][6], a[mi][7], bv.x, bv.y);
                }
            }
        }
    }

    if (MODE == 1 || MODE == 2) {
        uint4* dstBase = (MODE == 1) ? gT1p : gA0p;
        #pragma unroll
        for (int mi = 0; mi < MI; ++mi) {
            int r0 = m0 + wm + 16*mi + g;
            #pragma unroll
            for (int k = 0; k < 4; ++k) {
                int kb = (n0 + wn)/16 + k;
                float b0 = 0.f, b1 = 0.f, b2 = 0.f, b3 = 0.f;
                if (MODE == 2) {
                    int colBase = n0 + wn + 16*k;
                    b0 = aux1[colBase + 2*t];
                    b1 = aux1[colBase + 2*t + 1];
                    b2 = aux1[colBase + 2*t + 8];
                    b3 = aux1[colBase + 2*t + 9];
                }
                unsigned h0, l0, h1, l1;
                split2(acc[mi][2*k][0] + b0, acc[mi][2*k][1] + b1, h0, l0);
                split2(acc[mi][2*k+1][0] + b2, acc[mi][2*k+1][1] + b3, h1, l1);
                dstBase[((size_t)kb*M_ + r0)*4 + t] = make_uint4(h0, h1, l0, l1);
                split2(acc[mi][2*k][2] + b0, acc[mi][2*k][3] + b1, h0, l0);
                split2(acc[mi][2*k+1][2] + b2, acc[mi][2*k+1][3] + b3, h1, l1);
                dstBase[((size_t)kb*M_ + r0 + 8)*4 + t] = make_uint4(h0, h1, l0, l1);
            }
        }
        return;
    }

    #pragma unroll
    for (int mi = 0; mi < MI; ++mi)
        #pragma unroll
        for (int j = 0; j < 8; ++j)
            #pragma unroll
            for (int d = 0; d < 4; ++d) {
                int mm = m0 + wm + 16*mi + g + ((d >= 2) ? 8 : 0);
                int nn = n0 + wn + 8*j + 2*t + (d & 1);
                if (nn >= N) continue;
                float v = acc[mi][j][d];
                if (MODE == 0) {
                    if (nn < DI)           g_z[(size_t)mm*DI + nn] = v;
                    else if (nn < DI + CD) g_xbc[(size_t)mm*CD + nn - DI] = v;
                    else {
                        int h = nn - DI - CD;
                        float tt = v + aux1[h];
                        float sp = (tt > 20.f) ? tt : log1pf(expf(tt));
                        g_dadt[(size_t)mm*H_ + h] = make_float2(sp, expf(sp * (-expf(aux2[h]))));
                    }
                } else {
                    int b = mm >> 11, l = mm & (L_-1);
                    outp[((size_t)(b*OC) + nn)*L_ + l] = v;
                }
            }
}

// ------------------------- depthwise causal conv + SiLU -------------------
__global__ void __launch_bounds__(256)
dwconv_kernel(const float* __restrict__ w, const float* __restrict__ bias) {
    int idx = blockIdx.x*256 + threadIdx.x;
    if (idx >= B_*L_*CD) return;
    int c = idx % CD;
    int m = idx / CD;
    int l = m % L_;
    float acc = bias[c];
    #pragma unroll
    for (int k = 0; k < 4; ++k) {
        int l2 = l + k - 3;
        if (l2 >= 0) acc += g_xbc[(size_t)(m - 3 + k)*CD + c] * w[c*4 + k];
    }
    float s = 1.f / (1.f + expf(-acc));
    float val = acc * s;
    if (c < DI) {
        int h = c / 3, pp = c - h*3;
        ((float*)&g_xp4[m*H_ + h])[pp] = val;
    } else {
        g_bc[m*32 + (c - DI)] = val;
    }
}

// ------------------------- scan phases ------------------------------------
__global__ void __launch_bounds__(256) scanA_kernel() {
    int idx = blockIdx.x*256 + threadIdx.x;
    int n = idx & 15, c = (idx >> 4) & 15, h = (idx >> 8) & 255, b = idx >> 16;
    float s0 = 0.f, s1 = 0.f, s2 = 0.f, pr = 1.f;
    int mBase = b*L_ + c*CHUNK;
    #pragma unroll 4
    for (int t = 0; t < CHUNK; ++t) {
        int m = mBase + t;
        float2 dd = g_dadt[m*H_ + h];
        float4 xp = g_xp4[m*H_ + h];
        float w = dd.x * g_bc[m*32 + n];
        s0 = s0*dd.y + w*xp.x;
        s1 = s1*dd.y + w*xp.y;
        s2 = s2*dd.y + w*xp.z;
        pr *= dd.y;
    }
    int u = (b*H_ + h)*NC + c;
    g_cs[u*48 + n] = s0; g_cs[u*48 + 16 + n] = s1; g_cs[u*48 + 32 + n] = s2;
    if (n == 0) g_cp[u] = pr;
}
__global__ void __launch_bounds__(256) scanB_kernel() {
    int idx = blockIdx.x*256 + threadIdx.x;
    int n = idx & 15, h = (idx >> 4) & 255, b = idx >> 12;
    float c0 = 0.f, c1 = 0.f, c2 = 0.f;
    for (int c = 0; c < NC; ++c) {
        int u = (b*H_ + h)*NC + c;
        g_hs[u*48 + n] = c0; g_hs[u*48 + 16 + n] = c1; g_hs[u*48 + 32 + n] = c2;
        float pr = g_cp[u];
        c0 = c0*pr + g_cs[u*48 + n];
        c1 = c1*pr + g_cs[u*48 + 16 + n];
        c2 = c2*pr + g_cs[u*48 + 32 + n];
    }
}
__global__ void __launch_bounds__(256) scanC_kernel(const float* __restrict__ Dp) {
    int idx = blockIdx.x*256 + threadIdx.x;
    int n = idx & 15, c = (idx >> 4) & 15, h = (idx >> 8) & 255, b = idx >> 16;
    int u = (b*H_ + h)*NC + c;
    float s0 = g_hs[u*48 + n], s1 = g_hs[u*48 + 16 + n], s2 = g_hs[u*48 + 32 + n];
    float Dh = Dp[h];
    int mBase = b*L_ + c*CHUNK;
    #pragma unroll 4
    for (int t = 0; t < CHUNK; ++t) {
        int m = mBase + t;
        float2 dd = g_dadt[m*H_ + h];
        float4 xp = g_xp4[m*H_ + h];
        float Bn = g_bc[m*32 + n], Cn = g_bc[m*32 + 16 + n];
        float w = dd.x * Bn;
        s0 = s0*dd.y + w*xp.x;
        s1 = s1*dd.y + w*xp.y;
        s2 = s2*dd.y + w*xp.z;
        float y0 = s0*Cn, y1 = s1*Cn, y2 = s2*Cn;
        #pragma unroll
        for (int off = 8; off >= 1; off >>= 1) {
            y0 += __shfl_xor_sync(0xffffffffu, y0, off);
            y1 += __shfl_xor_sync(0xffffffffu, y1, off);
            y2 += __shfl_xor_sync(0xffffffffu, y2, off);
        }
        if (n == 0) {
            float* yo = &g_y[(size_t)m*DI + h*3];
            yo[0] = y0 + Dh*xp.x; yo[1] = y1 + Dh*xp.y; yo[2] = y2 + Dh*xp.z;
        }
    }
}

// ------------------------- gate + RMSNorm + pack for gemm1 ----------------
__global__ void __launch_bounds__(256)
gate_norm_kernel(const float* __restrict__ nw) {
    int m = blockIdx.x;
    int tid = threadIdx.x;
    __shared__ float red[8];
    __shared__ float ys[DI + DI/16];
    float yv[3];
    float acc = 0.f;
    #pragma unroll
    for (int j = 0; j < 3; ++j) {
        int e = tid*3 + j;
        float y = g_y[(size_t)m*DI + e];
        float z = g_z[(size_t)m*DI + e];
        float gg = y * (z / (1.f + expf(-z)));
        yv[j] = gg;
        acc += gg*gg;
    }
    #pragma unroll
    for (int off = 16; off >= 1; off >>= 1)
        acc += __shfl_xor_sync(0xffffffffu, acc, off);
    if ((tid & 31) == 0) red[tid >> 5] = acc;
    __syncthreads();
    if (tid == 0) {
        float t = 0.f;
        #pragma unroll
        for (int i = 0; i < 8; ++i) t += red[i];
        red[0] = rsqrtf(t / (float)DI + 1e-5f);
    }
    __syncthreads();
    float scale = red[0];
    #pragma unroll
    for (int j = 0; j < 3; ++j) {
        int e = tid*3 + j;
        ys[e + (e >> 4)] = yv[j] * scale * nw[e];
    }
    __syncthreads();
    if (tid < KB1) {
        float v[16];
        #pragma unroll
        for (int r = 0; r < 16; ++r) v[r] = ys[tid*17 + r];
        pack_block16(v, &gYp[((size_t)tid*M_ + m)*4]);
    }
}

// ------------------------- launch ----------------------------------------
#define SMEM128 (3*(2*128*4 + 1024)*16)   // 98304 B, TM=128
#define SMEM64  (3*(2*64*4  + 1024)*16)   // 73728 B, TM=64
extern "C" void kernel_launch(void* const* d_in, const int* in_sizes, int n_in,
                              void* d_out, int out_size) {
    const float* x           = (const float*)d_in[0];
    const float* conv_w      = (const float*)d_in[1];
    const float* conv_b      = (const float*)d_in[2];
    const float* in_proj_w   = (const float*)d_in[3];
    const float* dw_conv_w   = (const float*)d_in[4];
    const float* dw_conv_b   = (const float*)d_in[5];
    const float* dt_bias     = (const float*)d_in[6];
    const float* A_log       = (const float*)d_in[7];
    const float* Dp          = (const float*)d_in[8];
    const float* norm_w      = (const float*)d_in[9];
    const float* mamba_out_w = (const float*)d_in[10];
    const float* out_conv_w  = (const float*)d_in[11];
    float* out = (float*)d_out;

    uint4 *pW0, *pW1, *pA0, *pY, *pX, *pWc, *pT1, *pWo;
    cudaGetSymbolAddress((void**)&pW0, gW0p);
    cudaGetSymbolAddress((void**)&pW1, gW1p);
    cudaGetSymbolAddress((void**)&pA0, gA0p);
    cudaGetSymbolAddress((void**)&pY,  gYp);
    cudaGetSymbolAddress((void**)&pX,  gXp);
    cudaGetSymbolAddress((void**)&pWc, gWcp);
    cudaGetSymbolAddress((void**)&pT1, gT1p);
    cudaGetSymbolAddress((void**)&pWo, gWop);

    cudaFuncSetAttribute(hgemm_kernel<0,128,0>,   cudaFuncAttributeMaxDynamicSharedMemorySize, SMEM128);
    cudaFuncSetAttribute(hgemm_kernel<1,128,0>,   cudaFuncAttributeMaxDynamicSharedMemorySize, SMEM128);
    cudaFuncSetAttribute(hgemm_kernel<2,128,KBX>, cudaFuncAttributeMaxDynamicSharedMemorySize, SMEM128);
    cudaFuncSetAttribute(hgemm_kernel<3,64,KBT>,  cudaFuncAttributeMaxDynamicSharedMemorySize, SMEM64);

    pack_weights_kernel<<<(SEG3 + 255)/256, 256>>>(in_proj_w, mamba_out_w,
                                                   conv_w, out_conv_w);
    pack_X_kernel<<<(KBX*M_)/256, 256>>>(x);

    // conv_in: M=8192, N=256, K=4x128 (16 pairs) -> packed gA0p
    hgemm_kernel<2, 128, KBX><<<dim3(DM/128, M_/128), 256, SMEM128>>>(
        pX, pWc, DM, DM, 16, conv_b, nullptr, nullptr);

    // in_proj: M=8192, N=1824 (pad 1920), K=256 (8 pairs)
    hgemm_kernel<0, 128, 0><<<dim3(NP0/128, M_/128), 256, SMEM128>>>(
        pA0, pW0, NP0, DIP, 8, dt_bias, A_log, nullptr);

    dwconv_kernel<<<(B_*L_*CD + 255)/256, 256>>>(dw_conv_w, dw_conv_b);
    scanA_kernel<<<(B_*H_*NC*NS)/256, 256>>>();
    scanB_kernel<<<(B_*H_*NS)/256, 256>>>();
    scanC_kernel<<<(B_*H_*NC*NS)/256, 256>>>(Dp);
    gate_norm_kernel<<<M_, 256>>>(norm_w);

    // out_proj: M=8192, N=256, K=768 (24 pairs) -> packed gT1p
    hgemm_kernel<1, 128, 0><<<dim3(DM/128, M_/128), 256, SMEM128>>>(
        pY, pW1, DM, DM, 24, nullptr, nullptr, nullptr);

    // conv_out: M=8192 (TM=64), N=128, K=4x256 (32 pairs)
    hgemm_kernel<3, 64, KBT><<<dim3(OC/128, M_/64), 256, SMEM64>>>(
        pT1, pWo, OC, OC, 32, nullptr, nullptr, out);
}

// round 16
// speedup vs baseline: 2.0915x; 1.0133x over previous
#include <cuda_runtime.h>
#include <cuda_bf16.h>
#include <math.h>

// Problem constants
#define B_    4
#define L_    2048
#define DM    256     // d_model
#define DI    768     // d_inner
#define H_    256     // nheads
#define NS    16      // d_state
#define CD    800     // conv_dim = DI + 2*NS
#define DIP   1824    // d_in_proj
#define INC   128     // input channels
#define OC    128     // output channels
#define NC    16      // scan chunks
#define CHUNK 128     // L per chunk
#define M_    (B_*L_) // 8192 rows
#define NP0   1920    // padded N for gemm0 (15 * 128)
#define KB0   16      // 256/16 (in_proj K blocks)
#define KB1   48      // 768/16 (out_proj K blocks)
#define KBX   8       // 128/16 (x channels K blocks, per tap)
#define KBT   16      // 256/16 (t1 channels K blocks, per tap)

// ------------------------- scratch (device globals) -----------------------
__device__ float  g_z   [M_*DI];
__device__ float  g_xbc [M_*CD];
__device__ float  g_y   [M_*DI];
__device__ float2 g_dadt[M_*H_];
__device__ float4 g_xp4 [M_*H_];
__device__ float  g_bc  [M_*32];
__device__ float  g_cs  [B_*H_*NC*3*NS];
__device__ float  g_hs  [B_*H_*NC*3*NS];
__device__ float  g_cp  [B_*H_*NC];
// bf16-split packed operands: per (kblk,row): 4 x uint4 of
// [hi pair(2t,2t+1) | hi pair(2t+8,2t+9) | lo pair | lo pair]
__device__ uint4  gA0p[KB0*M_*4];
__device__ uint4  gW0p[KB0*NP0*4];
__device__ uint4  gYp [KB1*M_*4];
__device__ uint4  gW1p[KB1*DM*4];
__device__ uint4  gXp [KBX*M_*4];
__device__ uint4  gWcp[4*KBX*DM*4];
__device__ uint4  gT1p[KBT*M_*4];
__device__ uint4  gWop[4*KBT*OC*4];
__device__ uint4  g_zero4[4];

// ------------------------- bf16 split helpers -----------------------------
__device__ __forceinline__ void split2(float a, float b, unsigned &hw, unsigned &lw) {
    __nv_bfloat16 ah = __float2bfloat16(a);
    __nv_bfloat16 bh = __float2bfloat16(b);
    float ar = a - __bfloat162float(ah);
    float br = b - __bfloat162float(bh);
    __nv_bfloat16 al = __float2bfloat16(ar);
    __nv_bfloat16 bl = __float2bfloat16(br);
    hw = ((unsigned)__bfloat16_as_ushort(bh) << 16) | (unsigned)__bfloat16_as_ushort(ah);
    lw = ((unsigned)__bfloat16_as_ushort(bl) << 16) | (unsigned)__bfloat16_as_ushort(al);
}
__device__ __forceinline__ void pack_block16(const float* v, uint4* dst) {
    #pragma unroll
    for (int t = 0; t < 4; ++t) {
        unsigned h0, l0, h1, l1;
        split2(v[2*t],     v[2*t + 1], h0, l0);
        split2(v[2*t + 8], v[2*t + 9], h1, l1);
        dst[t] = make_uint4(h0, h1, l0, l1);
    }
}

// ------------------------- pack kernels ------------------------------------
__global__ void __launch_bounds__(256) pack_X_kernel(const float* __restrict__ x) {
    int idx = blockIdx.x*256 + threadIdx.x;       // kb*M + m, kb 0..7
    int kb = idx >> 13, m = idx & (M_ - 1);
    int b = m >> 11, l = m & 2047;
    float v[16];
    #pragma unroll
    for (int r = 0; r < 16; ++r) v[r] = x[(b*INC + kb*16 + r)*L_ + l];
    pack_block16(v, &gXp[(size_t)idx*4]);
}
#define SEG0 (KB0*NP0)
#define SEG1 (SEG0 + KB1*DM)
#define SEG2 (SEG1 + 4*KBX*DM)
#define SEG3 (SEG2 + 4*KBT*OC)
__global__ void __launch_bounds__(256)
pack_weights_kernel(const float* __restrict__ Wip, const float* __restrict__ Wmo,
                    const float* __restrict__ Wc,  const float* __restrict__ Wo) {
    int idx = blockIdx.x*256 + threadIdx.x;
    float v[16];
    if (idx < SEG0) {
        int kb = idx / NP0, n = idx % NP0;
        #pragma unroll
        for (int r = 0; r < 16; ++r)
            v[r] = (n < DIP) ? Wip[(kb*16 + r)*DIP + n] : 0.f;
        pack_block16(v, &gW0p[(size_t)idx*4]);
    } else if (idx < SEG1) {
        int i = idx - SEG0;
        int kb = i / DM, n = i % DM;
        #pragma unroll
        for (int r = 0; r < 16; ++r) v[r] = Wmo[(kb*16 + r)*DM + n];
        pack_block16(v, &gW1p[(size_t)i*4]);
    } else if (idx < SEG2) {
        int i = idx - SEG1;
        int kbe = i >> 8, co = i & 255;
        int tap = kbe >> 3, kbx = kbe & 7;
        #pragma unroll
        for (int r = 0; r < 16; ++r) v[r] = Wc[(co*INC + kbx*16 + r)*4 + tap];
        pack_block16(v, &gWcp[(size_t)i*4]);
    } else if (idx < SEG3) {
        int i = idx - SEG2;
        int kbe = i >> 7, o = i & 127;
        int tap = kbe >> 4, kbx = kbe & 15;
        #pragma unroll
        for (int r = 0; r < 16; ++r) v[r] = Wo[(o*DM + kbx*16 + r)*4 + tap];
        pack_block16(v, &gWop[(size_t)i*4]);
    }
}

// ------------------------- HMMA GEMM (bf16 3-term split, fp32 acc) --------
#define MMA_B16(d, a0,a1,a2,a3, b0,b1) \
    asm volatile("mma.sync.aligned.m16n8k16.row.col.f32.bf16.bf16.f32 " \
        "{%0,%1,%2,%3}, {%4,%5,%6,%7}, {%8,%9}, {%0,%1,%2,%3};" \
        : "+f"(d[0]), "+f"(d[1]), "+f"(d[2]), "+f"(d[3]) \
        : "r"(a0), "r"(a1), "r"(a2), "r"(a3), "r"(b0), "r"(b1))
#define CPA16(s, g) asm volatile("cp.async.cg.shared.global [%0], [%1], 16;" :: "r"(s), "l"(g))
#define CPCOMMIT()  asm volatile("cp.async.commit_group;")
#define CPWAIT1()   asm volatile("cp.async.wait_group 1;")

// TM x 128 CTA tile, 8 warps, warp tile (TM/4)x64. K-step 32, 3-stage ring
// with STATIC buffer bases (loop unrolled by 3 so stage pointers are
// compile-time offsets -> all LDS fold to base+immediate).
// MODE 0: in_proj epilogue | 1: ->gT1p packed | 2: conv_in +bias ->gA0p | 3: conv_out ->out
template<int MODE, int TM, int CONV_KBI>
__global__ void __launch_bounds__(256)
hgemm_kernel(const uint4* __restrict__ Ap, const uint4* __restrict__ Bp,
             int NPad, int N, int KBP,
             const float* __restrict__ aux1, const float* __restrict__ aux2,
             float* __restrict__ outp) {
    constexpr int AT = TM * 4;                // uint4 per 16-K A tile
    constexpr int STG = 2*AT + 1024;          // uint4 per stage (A0 A1 B0 B1)
    constexpr int MI = TM / 64;
    extern __shared__ uint4 sb[];
    int tid  = threadIdx.x;
    int m0   = blockIdx.y * TM, n0 = blockIdx.x * 128;
    int lane = tid & 31, warp = tid >> 5;
    int g = lane >> 2, t = lane & 3;
    int wm = (warp >> 1) * (TM/4), wn = (warp & 1) * 64;

    float acc[MI][8][4];
    #pragma unroll
    for (int mi = 0; mi < MI; ++mi)
        #pragma unroll
        for (int j = 0; j < 8; ++j)
            #pragma unroll
            for (int d = 0; d < 4; ++d) acc[mi][j][d] = 0.f;

    auto copy_pair = [&](int qp, uint4* st) {
        #pragma unroll
        for (int s = 0; s < 2; ++s) {
            int kbe = 2*qp + s;
            int kbx = kbe, shift = 0;
            if (CONV_KBI) { kbx = kbe & (CONV_KBI-1); shift = (kbe / CONV_KBI) - 1; }
            if (TM == 128) {
                int crow = tid >> 1, coff = (tid & 1) * 2;
                const uint4* asrc = Ap + ((size_t)kbx*M_ + m0 + crow + shift)*4 + coff;
                if (CONV_KBI) {
                    int ld = ((m0 + crow) & (L_-1)) + shift;
                    if ((unsigned)ld >= (unsigned)L_) asrc = g_zero4;
                }
                unsigned sa = (unsigned)__cvta_generic_to_shared(&st[s*AT + crow*4 + coff]);
                CPA16(sa,      asrc);
                CPA16(sa + 16, asrc + 1);
            } else {
                int arow = tid >> 2, aslot = tid & 3;
                const uint4* asrc = Ap + ((size_t)kbx*M_ + m0 + arow + shift)*4 + aslot;
                if (CONV_KBI) {
                    int ld = ((m0 + arow) & (L_-1)) + shift;
                    if ((unsigned)ld >= (unsigned)L_) asrc = g_zero4;
                }
                unsigned sa = (unsigned)__cvta_generic_to_shared(&st[s*AT + arow*4 + aslot]);
                CPA16(sa, asrc);
            }
            {
                int brow = tid >> 1, bcoff = (tid & 1) * 2;
                const uint4* bsrc = Bp + ((size_t)kbe*NPad + n0 + brow)*4 + bcoff;
                unsigned sB = (unsigned)__cvta_generic_to_shared(&st[2*AT + s*512 + brow*4 + bcoff]);
                CPA16(sB,      bsrc);
                CPA16(sB + 16, bsrc + 1);
            }
        }
    };

    auto compute_pair = [&](const uint4* st) {
        #pragma unroll
        for (int s = 0; s < 2; ++s) {
            const uint4* As = st + s*AT;
            const uint4* Bs = st + 2*AT + s*512;
            unsigned a[MI][8];
            #pragma unroll
            for (int mi = 0; mi < MI; ++mi) {
                uint4 v0 = As[(wm + 16*mi + g)*4 + t];
                uint4 v1 = As[(wm + 16*mi + g + 8)*4 + t];
                a[mi][0] = v0.x; a[mi][2] = v0.y; a[mi][4] = v0.z; a[mi][6] = v0.w;
                a[mi][1] = v1.x; a[mi][3] = v1.y; a[mi][5] = v1.z; a[mi][7] = v1.w;
            }
            #pragma unroll
            for (int j = 0; j < 8; ++j) {
                uint4 bv = Bs[(wn + 8*j + g)*4 + t];
                #pragma unroll
                for (int mi = 0; mi < MI; ++mi) {
                    MMA_B16(acc[mi][j], a[mi][0], a[mi][1], a[mi][2], a[mi][3], bv.x, bv.y);
                    MMA_B16(acc[mi][j], a[mi][0], a[mi][1], a[mi][2], a[mi][3], bv.z, bv.w);
                    MMA_B16(acc[mi][j], a[mi][4], a[mi][5], a[mi][6], a[mi][7], bv.x, bv.y);
                }
            }
        }
    };

    copy_pair(0, sb); CPCOMMIT();
    if (KBP > 1) copy_pair(1, sb + STG);
    CPCOMMIT();

    // 3-stage pipeline, statically unrolled so buffer bases are constants.
    for (int qp0 = 0; qp0 < KBP; qp0 += 3) {
        {
            CPWAIT1(); __syncthreads();
            if (qp0 + 2 < KBP) copy_pair(qp0 + 2, sb + 2*STG);
            CPCOMMIT();
            compute_pair(sb);
        }
        if (qp0 + 1 < KBP) {
            CPWAIT1(); __syncthreads();
            if (qp0 + 3 < KBP) copy_pair(qp0 + 3, sb);
            CPCOMMIT();
            compute_pair(sb + STG);
        }
        if (qp0 + 2 < KBP) {
            CPWAIT1(); __syncthreads();
            if (qp0 + 4 < KBP) copy_pair(qp0 + 4, sb + STG);
            CPCOMMIT();
            compute_pair(sb + 2*STG);
        }
    }

    if (MODE == 1 || MODE == 2) {
        uint4* dstBase = (MODE == 1) ? gT1p : gA0p;
        #pragma unroll
        for (int mi = 0; mi < MI; ++mi) {
            int r0 = m0 + wm + 16*mi + g;
            #pragma unroll
            for (int k = 0; k < 4; ++k) {
                int kb = (n0 + wn)/16 + k;
                float b0 = 0.f, b1 = 0.f, b2 = 0.f, b3 = 0.f;
                if (MODE == 2) {
                    int colBase = n0 + wn + 16*k;
                    b0 = aux1[colBase + 2*t];
                    b1 = aux1[colBase + 2*t + 1];
                    b2 = aux1[colBase + 2*t + 8];
                    b3 = aux1[colBase + 2*t + 9];
                }
                unsigned h0, l0, h1, l1;
                split2(acc[mi][2*k][0] + b0, acc[mi][2*k][1] + b1, h0, l0);
                split2(acc[mi][2*k+1][0] + b2, acc[mi][2*k+1][1] + b3, h1, l1);
                dstBase[((size_t)kb*M_ + r0)*4 + t] = make_uint4(h0, h1, l0, l1);
                split2(acc[mi][2*k][2] + b0, acc[mi][2*k][3] + b1, h0, l0);
                split2(acc[mi][2*k+1][2] + b2, acc[mi][2*k+1][3] + b3, h1, l1);
                dstBase[((size_t)kb*M_ + r0 + 8)*4 + t] = make_uint4(h0, h1, l0, l1);
            }
        }
        return;
    }

    #pragma unroll
    for (int mi = 0; mi < MI; ++mi)
        #pragma unroll
        for (int j = 0; j < 8; ++j)
            #pragma unroll
            for (int d = 0; d < 4; ++d) {
                int mm = m0 + wm + 16*mi + g + ((d >= 2) ? 8 : 0);
                int nn = n0 + wn + 8*j + 2*t + (d & 1);
                if (nn >= N) continue;
                float v = acc[mi][j][d];
                if (MODE == 0) {
                    if (nn < DI)           g_z[(size_t)mm*DI + nn] = v;
                    else if (nn < DI + CD) g_xbc[(size_t)mm*CD + nn - DI] = v;
                    else {
                        int h = nn - DI - CD;
                        float tt = v + aux1[h];
                        float sp = (tt > 20.f) ? tt : log1pf(expf(tt));
                        g_dadt[(size_t)mm*H_ + h] = make_float2(sp, expf(sp * (-expf(aux2[h]))));
                    }
                } else {
                    int b = mm >> 11, l = mm & (L_-1);
                    outp[((size_t)(b*OC) + nn)*L_ + l] = v;
                }
            }
}

// ------------------------- depthwise causal conv + SiLU -------------------
__global__ void __launch_bounds__(256)
dwconv_kernel(const float* __restrict__ w, const float* __restrict__ bias) {
    int idx = blockIdx.x*256 + threadIdx.x;
    if (idx >= B_*L_*CD) return;
    int c = idx % CD;
    int m = idx / CD;
    int l = m % L_;
    float acc = bias[c];
    #pragma unroll
    for (int k = 0; k < 4; ++k) {
        int l2 = l + k - 3;
        if (l2 >= 0) acc += g_xbc[(size_t)(m - 3 + k)*CD + c] * w[c*4 + k];
    }
    float s = 1.f / (1.f + expf(-acc));
    float val = acc * s;
    if (c < DI) {
        int h = c / 3, pp = c - h*3;
        ((float*)&g_xp4[m*H_ + h])[pp] = val;
    } else {
        g_bc[m*32 + (c - DI)] = val;
    }
}

// ------------------------- scan phases ------------------------------------
__global__ void __launch_bounds__(256) scanA_kernel() {
    int idx = blockIdx.x*256 + threadIdx.x;
    int n = idx & 15, c = (idx >> 4) & 15, h = (idx >> 8) & 255, b = idx >> 16;
    float s0 = 0.f, s1 = 0.f, s2 = 0.f, pr = 1.f;
    int mBase = b*L_ + c*CHUNK;
    #pragma unroll 4
    for (int t = 0; t < CHUNK; ++t) {
        int m = mBase + t;
        float2 dd = g_dadt[m*H_ + h];
        float4 xp = g_xp4[m*H_ + h];
        float w = dd.x * g_bc[m*32 + n];
        s0 = s0*dd.y + w*xp.x;
        s1 = s1*dd.y + w*xp.y;
        s2 = s2*dd.y + w*xp.z;
        pr *= dd.y;
    }
    int u = (b*H_ + h)*NC + c;
    g_cs[u*48 + n] = s0; g_cs[u*48 + 16 + n] = s1; g_cs[u*48 + 32 + n] = s2;
    if (n == 0) g_cp[u] = pr;
}
__global__ void __launch_bounds__(256) scanB_kernel() {
    int idx = blockIdx.x*256 + threadIdx.x;
    int n = idx & 15, h = (idx >> 4) & 255, b = idx >> 12;
    float c0 = 0.f, c1 = 0.f, c2 = 0.f;
    for (int c = 0; c < NC; ++c) {
        int u = (b*H_ + h)*NC + c;
        g_hs[u*48 + n] = c0; g_hs[u*48 + 16 + n] = c1; g_hs[u*48 + 32 + n] = c2;
        float pr = g_cp[u];
        c0 = c0*pr + g_cs[u*48 + n];
        c1 = c1*pr + g_cs[u*48 + 16 + n];
        c2 = c2*pr + g_cs[u*48 + 32 + n];
    }
}
__global__ void __launch_bounds__(256) scanC_kernel(const float* __restrict__ Dp) {
    int idx = blockIdx.x*256 + threadIdx.x;
    int n = idx & 15, c = (idx >> 4) & 15, h = (idx >> 8) & 255, b = idx >> 16;
    int u = (b*H_ + h)*NC + c;
    float s0 = g_hs[u*48 + n], s1 = g_hs[u*48 + 16 + n], s2 = g_hs[u*48 + 32 + n];
    float Dh = Dp[h];
    int mBase = b*L_ + c*CHUNK;
    #pragma unroll 4
    for (int t = 0; t < CHUNK; ++t) {
        int m = mBase + t;
        float2 dd = g_dadt[m*H_ + h];
        float4 xp = g_xp4[m*H_ + h];
        float Bn = g_bc[m*32 + n], Cn = g_bc[m*32 + 16 + n];
        float w = dd.x * Bn;
        s0 = s0*dd.y + w*xp.x;
        s1 = s1*dd.y + w*xp.y;
        s2 = s2*dd.y + w*xp.z;
        float y0 = s0*Cn, y1 = s1*Cn, y2 = s2*Cn;
        #pragma unroll
        for (int off = 8; off >= 1; off >>= 1) {
            y0 += __shfl_xor_sync(0xffffffffu, y0, off);
            y1 += __shfl_xor_sync(0xffffffffu, y1, off);
            y2 += __shfl_xor_sync(0xffffffffu, y2, off);
        }
        if (n == 0) {
            float* yo = &g_y[(size_t)m*DI + h*3];
            yo[0] = y0 + Dh*xp.x; yo[1] = y1 + Dh*xp.y; yo[2] = y2 + Dh*xp.z;
        }
    }
}

// ------------------------- gate + RMSNorm + pack for gemm1 ----------------
__global__ void __launch_bounds__(256)
gate_norm_kernel(const float* __restrict__ nw) {
    int m = blockIdx.x;
    int tid = threadIdx.x;
    __shared__ float red[8];
    __shared__ float ys[DI + DI/16];
    float yv[3];
    float acc = 0.f;
    #pragma unroll
    for (int j = 0; j < 3; ++j) {
        int e = tid*3 + j;
        float y = g_y[(size_t)m*DI + e];
        float z = g_z[(size_t)m*DI + e];
        float gg = y * (z / (1.f + expf(-z)));
        yv[j] = gg;
        acc += gg*gg;
    }
    #pragma unroll
    for (int off = 16; off >= 1; off >>= 1)
        acc += __shfl_xor_sync(0xffffffffu, acc, off);
    if ((tid & 31) == 0) red[tid >> 5] = acc;
    __syncthreads();
    if (tid == 0) {
        float t = 0.f;
        #pragma unroll
        for (int i = 0; i < 8; ++i) t += red[i];
        red[0] = rsqrtf(t / (float)DI + 1e-5f);
    }
    __syncthreads();
    float scale = red[0];
    #pragma unroll
    for (int j = 0; j < 3; ++j) {
        int e = tid*3 + j;
        ys[e + (e >> 4)] = yv[j] * scale * nw[e];
    }
    __syncthreads();
    if (tid < KB1) {
        float v[16];
        #pragma unroll
        for (int r = 0; r < 16; ++r) v[r] = ys[tid*17 + r];
        pack_block16(v, &gYp[((size_t)tid*M_ + m)*4]);
    }
}

// ------------------------- launch ----------------------------------------
#define SMEM128 (3*(2*128*4 + 1024)*16)   // 98304 B, TM=128
#define SMEM64  (3*(2*64*4  + 1024)*16)   // 73728 B, TM=64
extern "C" void kernel_launch(void* const* d_in, const int* in_sizes, int n_in,
                              void* d_out, int out_size) {
    const float* x           = (const float*)d_in[0];
    const float* conv_w      = (const float*)d_in[1];
    const float* conv_b      = (const float*)d_in[2];
    const float* in_proj_w   = (const float*)d_in[3];
    const float* dw_conv_w   = (const float*)d_in[4];
    const float* dw_conv_b   = (const float*)d_in[5];
    const float* dt_bias     = (const float*)d_in[6];
    const float* A_log       = (const float*)d_in[7];
    const float* Dp          = (const float*)d_in[8];
    const float* norm_w      = (const float*)d_in[9];
    const float* mamba_out_w = (const float*)d_in[10];
    const float* out_conv_w  = (const float*)d_in[11];
    float* out = (float*)d_out;

    uint4 *pW0, *pW1, *pA0, *pY, *pX, *pWc, *pT1, *pWo;
    cudaGetSymbolAddress((void**)&pW0, gW0p);
    cudaGetSymbolAddress((void**)&pW1, gW1p);
    cudaGetSymbolAddress((void**)&pA0, gA0p);
    cudaGetSymbolAddress((void**)&pY,  gYp);
    cudaGetSymbolAddress((void**)&pX,  gXp);
    cudaGetSymbolAddress((void**)&pWc, gWcp);
    cudaGetSymbolAddress((void**)&pT1, gT1p);
    cudaGetSymbolAddress((void**)&pWo, gWop);

    cudaFuncSetAttribute(hgemm_kernel<0,128,0>,  cudaFuncAttributeMaxDynamicSharedMemorySize, SMEM128);
    cudaFuncSetAttribute(hgemm_kernel<1,64,0>,   cudaFuncAttributeMaxDynamicSharedMemorySize, SMEM64);
    cudaFuncSetAttribute(hgemm_kernel<2,64,KBX>, cudaFuncAttributeMaxDynamicSharedMemorySize, SMEM64);
    cudaFuncSetAttribute(hgemm_kernel<3,64,KBT>, cudaFuncAttributeMaxDynamicSharedMemorySize, SMEM64);

    pack_weights_kernel<<<(SEG3 + 255)/256, 256>>>(in_proj_w, mamba_out_w,
                                                   conv_w, out_conv_w);
    pack_X_kernel<<<(KBX*M_)/256, 256>>>(x);

    // conv_in: M=8192 (TM=64 -> 256 CTAs), N=256, K=4x128 (16 pairs) -> gA0p
    hgemm_kernel<2, 64, KBX><<<dim3(DM/128, M_/64), 256, SMEM64>>>(
        pX, pWc, DM, DM, 16, conv_b, nullptr, nullptr);

    // in_proj: M=8192, N=1824 (pad 1920), K=256 (8 pairs), 960 CTAs
    hgemm_kernel<0, 128, 0><<<dim3(NP0/128, M_/128), 256, SMEM128>>>(
        pA0, pW0, NP0, DIP, 8, dt_bias, A_log, nullptr);

    dwconv_kernel<<<(B_*L_*CD + 255)/256, 256>>>(dw_conv_w, dw_conv_b);
    scanA_kernel<<<(B_*H_*NC*NS)/256, 256>>>();
    scanB_kernel<<<(B_*H_*NS)/256, 256>>>();
    scanC_kernel<<<(B_*H_*NC*NS)/256, 256>>>(Dp);
    gate_norm_kernel<<<M_, 256>>>(norm_w);

    // out_proj: M=8192 (TM=64 -> 256 CTAs), N=256, K=768 (24 pairs) -> gT1p
    hgemm_kernel<1, 64, 0><<<dim3(DM/128, M_/64), 256, SMEM64>>>(
        pY, pW1, DM, DM, 24, nullptr, nullptr, nullptr);

    // conv_out: M=8192 (TM=64), N=128, K=4x256 (32 pairs)
    hgemm_kernel<3, 64, KBT><<<dim3(OC/128, M_/64), 256, SMEM64>>>(
        pT1, pWo, OC, OC, 32, nullptr, nullptr, out);
}